// round 8
// baseline (speedup 1.0000x reference)
#include <cuda_runtime.h>
#include <cuda_bf16.h>
#include <math.h>
#include <stdint.h>

// Problem constants
#define BATCH   2
#define SEQ     2048
#define HID     4096
#define NHEADS  32
#define NKV     8
#define NREP    4
#define HD      128
#define SCALING 0.08838834764831845f           // 128^-0.5
#define QSCALE  0.1275429555686623f            // SCALING * log2(e)
#define NEG_BIG (-1.0e30f)

// ---------------------------------------------------------------------------
// Scratch (device globals)
// ---------------------------------------------------------------------------
__device__ float g_q[BATCH * NHEADS * SEQ * HD];
__device__ float g_k[BATCH * NKV * SEQ * HD];
__device__ float g_v[BATCH * NKV * SEQ * HD];

__device__ __nv_bfloat16 g_xhi[4096 * 4096], g_xlo[4096 * 4096];
__device__ __nv_bfloat16 g_wqT_hi[4096 * 4096], g_wqT_lo[4096 * 4096];
__device__ __nv_bfloat16 g_wkT_hi[1024 * 4096], g_wkT_lo[1024 * 4096];
__device__ __nv_bfloat16 g_wvT_hi[1024 * 4096], g_wvT_lo[1024 * 4096];
__device__ __nv_bfloat16 g_woT_hi[4096 * 4096], g_woT_lo[4096 * 4096];
__device__ __nv_bfloat16 g_ahi[4096 * 4096], g_alo[4096 * 4096];

__device__ __nv_bfloat16 g_qhi[BATCH * NHEADS * SEQ * HD], g_qlo[BATCH * NHEADS * SEQ * HD];
__device__ __nv_bfloat16 g_khi[BATCH * NKV * SEQ * HD],    g_klo[BATCH * NKV * SEQ * HD];
__device__ __nv_bfloat16 g_vhi[BATCH * NKV * SEQ * HD],    g_vlo[BATCH * NKV * SEQ * HD];

// ---------------------------------------------------------------------------
// PTX helpers
// ---------------------------------------------------------------------------
__device__ __forceinline__ uint32_t smem_u32(const void* p) {
    uint32_t a;
    asm("{ .reg .u64 t; cvta.to.shared.u64 t, %1; cvt.u32.u64 %0, t; }"
        : "=r"(a) : "l"(p));
    return a;
}

#define CP_ASYNC16(dst, src) \
    asm volatile("cp.async.cg.shared.global [%0], [%1], 16;" :: "r"(dst), "l"(src) : "memory")
#define CP_COMMIT() asm volatile("cp.async.commit_group;" ::: "memory")
#define CP_WAIT0()  asm volatile("cp.async.wait_group 0;" ::: "memory")
#define CP_WAIT1()  asm volatile("cp.async.wait_group 1;" ::: "memory")
#define CP_WAIT2()  asm volatile("cp.async.wait_group 2;" ::: "memory")

__device__ __forceinline__ void ldsm4(uint32_t* r, uint32_t addr) {
    asm volatile("ldmatrix.sync.aligned.m8n8.x4.shared.b16 {%0,%1,%2,%3}, [%4];"
        : "=r"(r[0]), "=r"(r[1]), "=r"(r[2]), "=r"(r[3]) : "r"(addr));
}
__device__ __forceinline__ void ldsm4t(uint32_t* r, uint32_t addr) {
    asm volatile("ldmatrix.sync.aligned.m8n8.x4.trans.shared.b16 {%0,%1,%2,%3}, [%4];"
        : "=r"(r[0]), "=r"(r[1]), "=r"(r[2]), "=r"(r[3]) : "r"(addr));
}

__device__ __forceinline__ void mma16816(float* d, const uint32_t* a, const uint32_t* b) {
    asm volatile(
        "mma.sync.aligned.m16n8k16.row.col.f32.bf16.bf16.f32 "
        "{%0,%1,%2,%3}, {%4,%5,%6,%7}, {%8,%9}, {%0,%1,%2,%3};"
        : "+f"(d[0]), "+f"(d[1]), "+f"(d[2]), "+f"(d[3])
        : "r"(a[0]), "r"(a[1]), "r"(a[2]), "r"(a[3]), "r"(b[0]), "r"(b[1]));
}

__device__ __forceinline__ uint32_t sw64(uint32_t off) {
    return off ^ ((off >> 3) & 0x30);
}

__device__ __forceinline__ uint32_t packbf(float lo, float hi) {
    uint32_t r;
    asm("cvt.rn.bf16x2.f32 %0, %1, %2;" : "=r"(r) : "f"(hi), "f"(lo));
    return r;
}

__device__ __forceinline__ float ex2(float x) {
    float r;
    asm("ex2.approx.f32 %0, %1;" : "=f"(r) : "f"(x));
    return r;
}

// ---------------------------------------------------------------------------
// Split kernels
// ---------------------------------------------------------------------------
__global__ void split_kernel(const float* __restrict__ in,
                             __nv_bfloat16* __restrict__ hi,
                             __nv_bfloat16* __restrict__ lo, int n)
{
    int i = (blockIdx.x * blockDim.x + threadIdx.x) * 4;
    if (i >= n) return;
    float4 v = *(const float4*)(in + i);
    float a[4] = {v.x, v.y, v.z, v.w};
    unsigned short hs[4], ls[4];
#pragma unroll
    for (int j = 0; j < 4; j++) {
        __nv_bfloat16 h = __float2bfloat16(a[j]);
        __nv_bfloat16 l = __float2bfloat16(a[j] - __bfloat162float(h));
        hs[j] = *(unsigned short*)&h;
        ls[j] = *(unsigned short*)&l;
    }
    *(ushort4*)(hi + i) = make_ushort4(hs[0], hs[1], hs[2], hs[3]);
    *(ushort4*)(lo + i) = make_ushort4(ls[0], ls[1], ls[2], ls[3]);
}

// Merged transpose+split for all 4 weights. in [4096, N] -> out [N, 4096].
__global__ void splitW_kernel(
    const float* __restrict__ wq, const float* __restrict__ wk,
    const float* __restrict__ wv, const float* __restrict__ wo,
    __nv_bfloat16* __restrict__ qh, __nv_bfloat16* __restrict__ ql,
    __nv_bfloat16* __restrict__ kh, __nv_bfloat16* __restrict__ kl,
    __nv_bfloat16* __restrict__ vh, __nv_bfloat16* __restrict__ vl,
    __nv_bfloat16* __restrict__ oh, __nv_bfloat16* __restrict__ ol)
{
    const int z = blockIdx.z;
    const float* in;
    __nv_bfloat16 *hi, *lo;
    int N;
    if (z == 0)      { in = wq; hi = qh; lo = ql; N = 4096; }
    else if (z == 1) { in = wk; hi = kh; lo = kl; N = 1024; }
    else if (z == 2) { in = wv; hi = vh; lo = vl; N = 1024; }
    else             { in = wo; hi = oh; lo = ol; N = 4096; }
    const int n0 = blockIdx.x * 32;
    if (n0 >= N) return;
    const int K = 4096;
    const int k0 = blockIdx.y * 32;

    __shared__ float t[32][33];
    const int tx = threadIdx.x, ty = threadIdx.y;
    for (int i = ty; i < 32; i += 8)
        t[i][tx] = in[(size_t)(k0 + i) * N + n0 + tx];
    __syncthreads();
    for (int i = ty; i < 32; i += 8) {
        float a = t[tx][i];
        __nv_bfloat16 h = __float2bfloat16(a);
        __nv_bfloat16 l = __float2bfloat16(a - __bfloat162float(h));
        size_t o = (size_t)(n0 + i) * K + k0 + tx;
        hi[o] = h;
        lo[o] = l;
    }
}

// RoPE + scale + split fused
__global__ void rope_split(const float* __restrict__ x,
                           const float* __restrict__ cosb,
                           const float* __restrict__ sinb,
                           __nv_bfloat16* __restrict__ hi,
                           __nv_bfloat16* __restrict__ lo,
                           int nh, int total, float scale)
{
    int idx = blockIdx.x * blockDim.x + threadIdx.x;
    if (idx >= total) return;
    const int d = idx & 63;
    const int row = idx >> 6;
    const int s = row & (SEQ - 1);
    const int b = (row / SEQ) / nh;
    const float* xr = x + (size_t)row * HD;
    const float* cb = cosb + ((size_t)b * SEQ + s) * HD;
    const float* sb = sinb + ((size_t)b * SEQ + s) * HD;
    const float x0 = xr[d];
    const float x1 = xr[d + 64];
    const float y0 = (x0 * cb[d]      - x1 * sb[d])      * scale;
    const float y1 = (x1 * cb[d + 64] + x0 * sb[d + 64]) * scale;
    const size_t o = (size_t)row * HD + d;
    __nv_bfloat16 h0 = __float2bfloat16(y0);
    __nv_bfloat16 h1 = __float2bfloat16(y1);
    hi[o]      = h0;
    hi[o + 64] = h1;
    lo[o]      = __float2bfloat16(y0 - __bfloat162float(h0));
    lo[o + 64] = __float2bfloat16(y1 - __bfloat162float(h1));
}

// ---------------------------------------------------------------------------
// mma.sync GEMM v2: BM=256, BN=128, BK=32, 512 threads (16 warps, 64x32/warp).
// Traffic/compute ratio 31.7 B/cyc/SM — under the LTS cap (~43), unlike v1 (86).
// 3-stage cp.async pipeline. 3-pass bf16 hi/lo split.
// ---------------------------------------------------------------------------
#define GT2_SMEM (3 * 49152 + 1024)

template <int MODE>
__global__ __launch_bounds__(512, 1) void gemm_mma2(
    const __nv_bfloat16* __restrict__ Ahi, const __nv_bfloat16* __restrict__ Alo,
    const __nv_bfloat16* __restrict__ Bhi, const __nv_bfloat16* __restrict__ Blo,
    float* __restrict__ C, int M, int N, int K, int nh)
{
    extern __shared__ char dsm_raw[];
    char* dsm = (char*)(((uintptr_t)dsm_raw + 1023) & ~(uintptr_t)1023);
    const uint32_t sm_base = smem_u32(dsm);

    const int tid = threadIdx.x;
    const int wid = tid >> 5;
    const int lane = tid & 31;
    const int wm = wid & 3;        // 4 warp-rows * 64
    const int wn = wid >> 2;       // 4 warp-cols * 32
    const int m0 = blockIdx.y * 256;
    const int n0 = blockIdx.x * 128;

    // stage: [Ahi 16KB][Alo 16KB][Bhi 8KB][Blo 8KB] = 48KB; rows of 64B
    auto load_chunk = [&](int stage, int c) {
        const int k0 = c << 5;
        const uint32_t stb = sm_base + stage * 49152u;
#pragma unroll
        for (int it = 0; it < 6; it++) {
            int g = tid + it * 512;
            if (g < 2048) {
                int arr = g >> 10;
                int rem = g & 1023;
                int r = rem >> 2;
                int cg = rem & 3;
                const __nv_bfloat16* src = (arr ? Alo : Ahi) + (size_t)(m0 + r) * K + k0 + cg * 8;
                uint32_t off = sw64((uint32_t)(r * 64 + cg * 16));
                CP_ASYNC16(stb + arr * 16384u + off, src);
            } else {
                int g2 = g - 2048;
                int arr = g2 >> 9;
                int rem = g2 & 511;
                int r = rem >> 2;
                int cg = rem & 3;
                const __nv_bfloat16* src = (arr ? Blo : Bhi) + (size_t)(n0 + r) * K + k0 + cg * 8;
                uint32_t off = sw64((uint32_t)(r * 64 + cg * 16));
                CP_ASYNC16(stb + 32768u + arr * 8192u + off, src);
            }
        }
        CP_COMMIT();
    };

    float acc[4][4][4];
#pragma unroll
    for (int mt = 0; mt < 4; mt++)
#pragma unroll
        for (int nt = 0; nt < 4; nt++)
#pragma unroll
            for (int i = 0; i < 4; i++) acc[mt][nt][i] = 0.f;

    const int NC = K >> 5;
    load_chunk(0, 0);
    load_chunk(1, 1);

    const uint32_t a_row = lane & 15;
    const uint32_t a_c16 = (lane >> 4) * 16;
    const uint32_t b_row = ((lane >> 4) & 1) * 8 + (lane & 7);
    const uint32_t b_c16 = ((lane >> 3) & 1) * 16;

    for (int c = 0; c < NC; c++) {
        if (c + 2 < NC) {
            load_chunk((c + 2) % 3, c + 2);
            CP_WAIT2();
        } else {
            CP_WAIT0();
        }
        __syncthreads();

        const uint32_t stb = sm_base + (uint32_t)(c % 3) * 49152u;
        const uint32_t Ah = stb, Al = stb + 16384u, Bh = stb + 32768u, Bl = stb + 40960u;

#pragma unroll
        for (int kt = 0; kt < 2; kt++) {
            uint32_t bhf[2][4], blf[2][4];
#pragma unroll
            for (int p = 0; p < 2; p++) {
                uint32_t off = sw64((wn * 32 + p * 16 + b_row) * 64 + kt * 32 + b_c16);
                ldsm4(bhf[p], Bh + off);
                ldsm4(blf[p], Bl + off);
            }
#pragma unroll
            for (int mt = 0; mt < 4; mt++) {
                uint32_t ah[4], al[4];
                uint32_t off = sw64((wm * 64 + mt * 16 + a_row) * 64 + kt * 32 + a_c16);
                ldsm4(ah, Ah + off);
                ldsm4(al, Al + off);
#pragma unroll
                for (int nt = 0; nt < 4; nt++)
                    mma16816(acc[mt][nt], ah, &bhf[nt >> 1][(nt & 1) * 2]);
#pragma unroll
                for (int nt = 0; nt < 4; nt++)
                    mma16816(acc[mt][nt], ah, &blf[nt >> 1][(nt & 1) * 2]);
#pragma unroll
                for (int nt = 0; nt < 4; nt++)
                    mma16816(acc[mt][nt], al, &bhf[nt >> 1][(nt & 1) * 2]);
            }
        }
        __syncthreads();
    }

    // epilogue
    const int mr = m0 + wm * 64 + (lane >> 2);
    const int nc = n0 + wn * 32 + (lane & 3) * 2;
#pragma unroll
    for (int mt = 0; mt < 4; mt++) {
#pragma unroll
        for (int nt = 0; nt < 4; nt++) {
#pragma unroll
            for (int half = 0; half < 2; half++) {
                const int m = mr + mt * 16 + half * 8;
                const int n = nc + nt * 8;
                float2 v = make_float2(acc[mt][nt][half * 2], acc[mt][nt][half * 2 + 1]);
                if (MODE == 0) {
                    *(float2*)&C[(size_t)m * N + n] = v;
                } else {
                    const int b = m >> 11;
                    const int s = m & (SEQ - 1);
                    const int h = n >> 7;
                    const int d = n & (HD - 1);
                    *(float2*)&C[((size_t)(b * nh + h) * SEQ + s) * HD + d] = v;
                }
            }
        }
    }
}

// ---------------------------------------------------------------------------
// Flash attention v3 (unchanged from round 7)
// ---------------------------------------------------------------------------
#define FLB_SMEM (196608)
#define NQT (SEQ / 128)   // 16

__global__ __launch_bounds__(256) void flash_mma(
    const __nv_bfloat16* __restrict__ Qhi, const __nv_bfloat16* __restrict__ Qlo,
    const __nv_bfloat16* __restrict__ Khi, const __nv_bfloat16* __restrict__ Klo,
    const __nv_bfloat16* __restrict__ Vhi, const __nv_bfloat16* __restrict__ Vlo,
    __nv_bfloat16* __restrict__ Ohi, __nv_bfloat16* __restrict__ Olo)
{
    extern __shared__ char dsm[];
    const uint32_t smQ = smem_u32(dsm);
    const uint32_t smK = smQ + 65536u;
    const uint32_t smV = smK + 65536u;

    const int tid = threadIdx.x;
    const int w = tid >> 5;
    const int lane = tid & 31;
    const int qt = NQT - 1 - blockIdx.x;
    const int bh = blockIdx.y;
    const int b = bh / NHEADS;
    const int h = bh % NHEADS;
    const int kvh = h / NREP;
    const int q0 = qt * 128;

    const size_t qoff = ((size_t)(b * NHEADS + h) * SEQ + q0) * HD;
    const size_t kvbase = (size_t)(b * NKV + kvh) * SEQ * HD;

    auto load_K = [&](int stage, int kt) {
        const int k0 = kt * 64;
        const uint32_t stb = smK + stage * 32768u;
#pragma unroll
        for (int it = 0; it < 8; it++) {
            int g = tid + it * 256;
            int arr = g >> 10;
            int rem = g & 1023;
            int r = rem >> 4;
            int gg = rem & 15;
            const __nv_bfloat16* src = (arr ? Klo : Khi) + kvbase + (size_t)(k0 + r) * HD + gg * 8;
            uint32_t dst = stb + arr * 16384u + (gg >> 2) * 4096u
                         + sw64((uint32_t)(r * 64 + (gg & 3) * 16));
            CP_ASYNC16(dst, src);
        }
    };
    auto load_V = [&](int stage, int kt) {
        const int k0 = kt * 64;
        const uint32_t stb = smV + stage * 32768u;
#pragma unroll
        for (int it = 0; it < 8; it++) {
            int g = tid + it * 256;
            int arr = g >> 10;
            int rem = g & 1023;
            int r = rem >> 4;
            int gg = rem & 15;
            const __nv_bfloat16* src = (arr ? Vlo : Vhi) + kvbase + (size_t)(k0 + r) * HD + gg * 8;
            uint32_t dst = stb + arr * 16384u + (gg >> 2) * 4096u
                         + sw64((uint32_t)(r * 64 + (gg & 3) * 16));
            CP_ASYNC16(dst, src);
        }
    };

    {
#pragma unroll
        for (int it = 0; it < 16; it++) {
            int g = tid + it * 256;
            int arr = g >> 11;
            int rem = g & 2047;
            int r = rem >> 4;
            int gg = rem & 15;
            const __nv_bfloat16* src = (arr ? Qlo : Qhi) + qoff + (size_t)r * HD + gg * 8;
            uint32_t dst = smQ + arr * 32768u + (gg >> 2) * 8192u
                         + sw64((uint32_t)(r * 64 + (gg & 3) * 16));
            CP_ASYNC16(dst, src);
        }
    }
    load_K(0, 0);
    CP_COMMIT();
    const int nkt = 2 * qt + 2;
    if (nkt > 1) load_K(1, 1);
    load_V(0, 0);
    CP_COMMIT();

    float o[16][4];
#pragma unroll
    for (int nt = 0; nt < 16; nt++)
#pragma unroll
        for (int e = 0; e < 4; e++) o[nt][e] = 0.f;
    float m_prev[2] = {NEG_BIG, NEG_BIG};
    float l[2] = {0.f, 0.f};

    const uint32_t a_row = w * 16 + (lane & 15);
    const uint32_t a_c16 = (lane >> 4) * 16;
    const uint32_t b_row = ((lane >> 4) & 1) * 8 + (lane & 7);
    const uint32_t b_c16 = ((lane >> 3) & 1) * 16;
    const uint32_t v_row = (lane & 7) + ((lane >> 3) & 1) * 8;
    const uint32_t v_c16 = (lane >> 4) * 16;

    float sA[8][4], sB[8][4];

    auto do_qk = [&](int kt, float (*sn)[4]) {
        const uint32_t Kst = smK + (uint32_t)(kt & 1) * 32768u;
        const uint32_t Kh = Kst, Kl = Kst + 16384u;
#pragma unroll
        for (int j = 0; j < 8; j++)
#pragma unroll
            for (int e = 0; e < 4; e++) sn[j][e] = 0.f;
#pragma unroll
        for (int ks = 0; ks < 8; ks++) {
            const uint32_t qoffb = (ks >> 1) * 8192u
                + sw64(a_row * 64 + (ks & 1) * 32 + a_c16);
            uint32_t qh[4], ql[4];
            ldsm4(qh, smQ + qoffb);
            ldsm4(ql, smQ + 32768u + qoffb);
            uint32_t kh[4][4], klf[4][4];
#pragma unroll
            for (int p = 0; p < 4; p++) {
                const uint32_t koffb = (ks >> 1) * 4096u
                    + sw64((b_row + p * 16) * 64 + (ks & 1) * 32 + b_c16);
                ldsm4(kh[p], Kh + koffb);
                ldsm4(klf[p], Kl + koffb);
            }
#pragma unroll
            for (int j = 0; j < 8; j++)
                mma16816(sn[j], qh, &kh[j >> 1][(j & 1) * 2]);
#pragma unroll
            for (int j = 0; j < 8; j++)
                mma16816(sn[j], qh, &klf[j >> 1][(j & 1) * 2]);
#pragma unroll
            for (int j = 0; j < 8; j++)
                mma16816(sn[j], ql, &kh[j >> 1][(j & 1) * 2]);
        }
    };

    auto do_softmax_pv = [&](int kt, float (*s)[4]) {
        const bool diag = (kt >= nkt - 2);
        if (diag) {
            const int k0 = kt * 64;
#pragma unroll
            for (int j = 0; j < 8; j++)
#pragma unroll
                for (int e = 0; e < 4; e++) {
                    const int cglob = k0 + j * 8 + (lane & 3) * 2 + (e & 1);
                    const int rglob = q0 + w * 16 + (lane >> 2) + (e >> 1) * 8;
                    if (cglob > rglob) s[j][e] = NEG_BIG;
                }
        }

        float mx0 = NEG_BIG, mx1 = NEG_BIG;
#pragma unroll
        for (int j = 0; j < 8; j++) {
            mx0 = fmaxf(mx0, fmaxf(s[j][0], s[j][1]));
            mx1 = fmaxf(mx1, fmaxf(s[j][2], s[j][3]));
        }
        mx0 = fmaxf(mx0, __shfl_xor_sync(0xffffffffu, mx0, 1));
        mx0 = fmaxf(mx0, __shfl_xor_sync(0xffffffffu, mx0, 2));
        mx1 = fmaxf(mx1, __shfl_xor_sync(0xffffffffu, mx1, 1));
        mx1 = fmaxf(mx1, __shfl_xor_sync(0xffffffffu, mx1, 2));

        const float mn0 = fmaxf(m_prev[0], mx0);
        const float mn1 = fmaxf(m_prev[1], mx1);
        const float corr0 = ex2(m_prev[0] - mn0);
        const float corr1 = ex2(m_prev[1] - mn1);
        m_prev[0] = mn0;
        m_prev[1] = mn1;

        float rs0 = 0.f, rs1 = 0.f;
#pragma unroll
        for (int j = 0; j < 8; j++) {
            s[j][0] = ex2(s[j][0] - mn0);
            s[j][1] = ex2(s[j][1] - mn0);
            s[j][2] = ex2(s[j][2] - mn1);
            s[j][3] = ex2(s[j][3] - mn1);
            rs0 += s[j][0] + s[j][1];
            rs1 += s[j][2] + s[j][3];
        }
        rs0 += __shfl_xor_sync(0xffffffffu, rs0, 1);
        rs0 += __shfl_xor_sync(0xffffffffu, rs0, 2);
        rs1 += __shfl_xor_sync(0xffffffffu, rs1, 1);
        rs1 += __shfl_xor_sync(0xffffffffu, rs1, 2);
        l[0] = l[0] * corr0 + rs0;
        l[1] = l[1] * corr1 + rs1;

#pragma unroll
        for (int nt = 0; nt < 16; nt++) {
            o[nt][0] *= corr0; o[nt][1] *= corr0;
            o[nt][2] *= corr1; o[nt][3] *= corr1;
        }

        const uint32_t Vst = smV + (uint32_t)(kt & 1) * 32768u;
        const uint32_t Vh = Vst, Vl = Vst + 16384u;
#pragma unroll
        for (int ks = 0; ks < 4; ks++) {
            const int j0 = 2 * ks, j1 = 2 * ks + 1;
            uint32_t phi[4], plo[4];
            {
                float hf[8], lf[8];
#pragma unroll
                for (int e = 0; e < 4; e++) {
                    float p0 = s[j0][e];
                    float h0 = __bfloat162float(__float2bfloat16(p0));
                    hf[e] = h0; lf[e] = p0 - h0;
                    float p1 = s[j1][e];
                    float h1 = __bfloat162float(__float2bfloat16(p1));
                    hf[4 + e] = h1; lf[4 + e] = p1 - h1;
                }
                phi[0] = packbf(hf[0], hf[1]);
                phi[1] = packbf(hf[2], hf[3]);
                phi[2] = packbf(hf[4], hf[5]);
                phi[3] = packbf(hf[6], hf[7]);
                plo[0] = packbf(lf[0], lf[1]);
                plo[1] = packbf(lf[2], lf[3]);
                plo[2] = packbf(lf[4], lf[5]);
                plo[3] = packbf(lf[6], lf[7]);
            }
#pragma unroll
            for (int c = 0; c < 4; c++) {
                uint32_t vh0[4], vh1[4], vl0[4], vl1[4];
                const uint32_t vb0 = c * 4096u + sw64((ks * 16 + v_row) * 64 + v_c16);
                const uint32_t vb1 = c * 4096u + sw64((ks * 16 + v_row) * 64 + 32 + v_c16);
                ldsm4t(vh0, Vh + vb0);
                ldsm4t(vh1, Vh + vb1);
                ldsm4t(vl0, Vl + vb0);
                ldsm4t(vl1, Vl + vb1);
                mma16816(o[c * 4 + 0], phi, vh0 + 0);
                mma16816(o[c * 4 + 1], phi, vh0 + 2);
                mma16816(o[c * 4 + 2], phi, vh1 + 0);
                mma16816(o[c * 4 + 3], phi, vh1 + 2);
                mma16816(o[c * 4 + 0], phi, vl0 + 0);
                mma16816(o[c * 4 + 1], phi, vl0 + 2);
                mma16816(o[c * 4 + 2], phi, vl1 + 0);
                mma16816(o[c * 4 + 3], phi, vl1 + 2);
                mma16816(o[c * 4 + 0], plo, vh0 + 0);
                mma16816(o[c * 4 + 1], plo, vh0 + 2);
                mma16816(o[c * 4 + 2], plo, vh1 + 0);
                mma16816(o[c * 4 + 3], plo, vh1 + 2);
            }
        }
    };

    CP_WAIT1();
    __syncthreads();
    do_qk(0, sA);

    auto body = [&](int i, float (*scur)[4], float (*snxt)[4]) {
        CP_WAIT0();
        __syncthreads();
        if (i + 1 < nkt) load_V((i + 1) & 1, i + 1);
        if (i + 2 < nkt) load_K((i + 2) & 1, i + 2);
        CP_COMMIT();
        if (i + 1 < nkt) do_qk(i + 1, snxt);
        do_softmax_pv(i, scur);
    };

    for (int i = 0; i < nkt; i += 2) {
        body(i, sA, sB);
        if (i + 1 < nkt) body(i + 1, sB, sA);
    }

    const float inv0 = 1.f / l[0];
    const float inv1 = 1.f / l[1];
    const int row0 = q0 + w * 16 + (lane >> 2);
#pragma unroll
    for (int nt = 0; nt < 16; nt++) {
        const int d = nt * 8 + (lane & 3) * 2;
        const size_t o0 = ((size_t)(b * SEQ + row0) * NHEADS + h) * HD + d;
        const size_t o1 = ((size_t)(b * SEQ + row0 + 8) * NHEADS + h) * HD + d;
        float v00 = o[nt][0] * inv0, v01 = o[nt][1] * inv0;
        float v10 = o[nt][2] * inv1, v11 = o[nt][3] * inv1;
        __nv_bfloat16 h00 = __float2bfloat16(v00), h01 = __float2bfloat16(v01);
        __nv_bfloat16 h10 = __float2bfloat16(v10), h11 = __float2bfloat16(v11);
        *(uint32_t*)&Ohi[o0] = packbf(v00, v01);
        *(uint32_t*)&Ohi[o1] = packbf(v10, v11);
        *(uint32_t*)&Olo[o0] = packbf(v00 - __bfloat162float(h00), v01 - __bfloat162float(h01));
        *(uint32_t*)&Olo[o1] = packbf(v10 - __bfloat162float(h10), v11 - __bfloat162float(h11));
    }
}

// ---------------------------------------------------------------------------
extern "C" void kernel_launch(void* const* d_in, const int* in_sizes, int n_in,
                              void* d_out, int out_size)
{
    const float* X    = (const float*)d_in[0];
    const float* cosb = (const float*)d_in[1];
    const float* sinb = (const float*)d_in[2];
    const float* wq = (const float*)d_in[4];
    const float* wk = (const float*)d_in[5];
    const float* wv = (const float*)d_in[6];
    const float* wo = (const float*)d_in[7];
    float* out = (float*)d_out;

    void *pq, *pk, *pv;
    cudaGetSymbolAddress(&pq, g_q);
    cudaGetSymbolAddress(&pk, g_k);
    cudaGetSymbolAddress(&pv, g_v);
    float* Qb = (float*)pq;
    float* Kb = (float*)pk;
    float* Vb = (float*)pv;

    void *pxh, *pxl, *pqh, *pql, *pkh, *pkl, *pvh, *pvl, *poh, *pol, *pah, *pal;
    cudaGetSymbolAddress(&pxh, g_xhi);   cudaGetSymbolAddress(&pxl, g_xlo);
    cudaGetSymbolAddress(&pqh, g_wqT_hi); cudaGetSymbolAddress(&pql, g_wqT_lo);
    cudaGetSymbolAddress(&pkh, g_wkT_hi); cudaGetSymbolAddress(&pkl, g_wkT_lo);
    cudaGetSymbolAddress(&pvh, g_wvT_hi); cudaGetSymbolAddress(&pvl, g_wvT_lo);
    cudaGetSymbolAddress(&poh, g_woT_hi); cudaGetSymbolAddress(&pol, g_woT_lo);
    cudaGetSymbolAddress(&pah, g_ahi);   cudaGetSymbolAddress(&pal, g_alo);
    __nv_bfloat16 *Xhi = (__nv_bfloat16*)pxh, *Xlo = (__nv_bfloat16*)pxl;
    __nv_bfloat16 *WqHi = (__nv_bfloat16*)pqh, *WqLo = (__nv_bfloat16*)pql;
    __nv_bfloat16 *WkHi = (__nv_bfloat16*)pkh, *WkLo = (__nv_bfloat16*)pkl;
    __nv_bfloat16 *WvHi = (__nv_bfloat16*)pvh, *WvLo = (__nv_bfloat16*)pvl;
    __nv_bfloat16 *WoHi = (__nv_bfloat16*)poh, *WoLo = (__nv_bfloat16*)pol;
    __nv_bfloat16 *AtHi = (__nv_bfloat16*)pah, *AtLo = (__nv_bfloat16*)pal;

    void *pfqh, *pfql, *pfkh, *pfkl, *pfvh, *pfvl;
    cudaGetSymbolAddress(&pfqh, g_qhi); cudaGetSymbolAddress(&pfql, g_qlo);
    cudaGetSymbolAddress(&pfkh, g_khi); cudaGetSymbolAddress(&pfkl, g_klo);
    cudaGetSymbolAddress(&pfvh, g_vhi); cudaGetSymbolAddress(&pfvl, g_vlo);
    __nv_bfloat16 *FQh = (__nv_bfloat16*)pfqh, *FQl = (__nv_bfloat16*)pfql;
    __nv_bfloat16 *FKh = (__nv_bfloat16*)pfkh, *FKl = (__nv_bfloat16*)pfkl;
    __nv_bfloat16 *FVh = (__nv_bfloat16*)pfvh, *FVl = (__nv_bfloat16*)pfvl;

    static bool attr_set = false;
    if (!attr_set) {
        cudaFuncSetAttribute(gemm_mma2<0>, cudaFuncAttributeMaxDynamicSharedMemorySize, GT2_SMEM);
        cudaFuncSetAttribute(gemm_mma2<1>, cudaFuncAttributeMaxDynamicSharedMemorySize, GT2_SMEM);
        cudaFuncSetAttribute(flash_mma, cudaFuncAttributeMaxDynamicSharedMemorySize, FLB_SMEM);
        attr_set = true;
    }

    const int M = BATCH * SEQ;   // 4096

    // 1: split X; 2: merged weight split; 3: gemm Q (ncu capture slot)
    split_kernel<<<(M * HID / 4 + 255) / 256, 256>>>(X, Xhi, Xlo, M * HID);
    splitW_kernel<<<dim3(128, 128, 4), dim3(32, 8)>>>(
        wq, wk, wv, wo, WqHi, WqLo, WkHi, WkLo, WvHi, WvLo, WoHi, WoLo);

    gemm_mma2<1><<<dim3(32, 16), 512, GT2_SMEM>>>(Xhi, Xlo, WqHi, WqLo, Qb, M, 4096, HID, NHEADS);
    gemm_mma2<1><<<dim3(8, 16), 512, GT2_SMEM>>>(Xhi, Xlo, WkHi, WkLo, Kb, M, 1024, HID, NKV);
    gemm_mma2<1><<<dim3(8, 16), 512, GT2_SMEM>>>(Xhi, Xlo, WvHi, WvLo, Vb, M, 1024, HID, NKV);

    // RoPE + split (Q pre-scaled by SCALING*log2e); plain split for V
    {
        int totq = BATCH * NHEADS * SEQ * 64;
        rope_split<<<(totq + 255) / 256, 256>>>(Qb, cosb, sinb, FQh, FQl, NHEADS, totq, QSCALE);
        int totk = BATCH * NKV * SEQ * 64;
        rope_split<<<(totk + 255) / 256, 256>>>(Kb, cosb, sinb, FKh, FKl, NKV, totk, 1.0f);
        int nkv = BATCH * NKV * SEQ * HD;
        split_kernel<<<(nkv / 4 + 255) / 256, 256>>>(Vb, FVh, FVl, nkv);
    }

    // Flash attention -> attn hi/lo [b,s,h,d]
    flash_mma<<<dim3(NQT, BATCH * NHEADS), 256, FLB_SMEM>>>(
        FQh, FQl, FKh, FKl, FVh, FVl, AtHi, AtLo);

    // Output projection
    gemm_mma2<0><<<dim3(32, 16), 512, GT2_SMEM>>>(AtHi, AtLo, WoHi, WoLo, out, M, HID, 4096, 0);

    (void)in_sizes; (void)n_in; (void)out_size;
}

// round 9
// speedup vs baseline: 1.6051x; 1.6051x over previous
#include <cuda_runtime.h>
#include <cuda_bf16.h>
#include <cuda_fp16.h>
#include <math.h>
#include <stdint.h>

// Problem constants
#define BATCH   2
#define SEQ     2048
#define HID     4096
#define NHEADS  32
#define NKV     8
#define NREP    4
#define HD      128
#define SCALING 0.08838834764831845f           // 128^-0.5
#define QSCALE  0.1275429555686623f            // SCALING * log2(e)
#define NEG_BIG (-1.0e30f)

// ---------------------------------------------------------------------------
// Scratch (device globals)
// ---------------------------------------------------------------------------
__device__ float g_q[BATCH * NHEADS * SEQ * HD];
__device__ float g_k[BATCH * NKV * SEQ * HD];
__device__ float g_v[BATCH * NKV * SEQ * HD];

// fp16 GEMM operands
__device__ __half g_xf16[4096 * 4096];
__device__ __half g_wqT_hi[4096 * 4096], g_wqT_lo[4096 * 4096];
__device__ __half g_wkT_hi[1024 * 4096], g_wkT_lo[1024 * 4096];
__device__ __half g_wvT_hi[1024 * 4096], g_wvT_lo[1024 * 4096];
__device__ __half g_woT_hi[4096 * 4096], g_woT_lo[4096 * 4096];
__device__ __half g_af16[4096 * 4096];        // attn output (fp16 single)

// flash operands: Q/K bf16 hi/lo (3-pass QK), V fp16 single
__device__ __nv_bfloat16 g_qhi[BATCH * NHEADS * SEQ * HD], g_qlo[BATCH * NHEADS * SEQ * HD];
__device__ __nv_bfloat16 g_khi[BATCH * NKV * SEQ * HD],    g_klo[BATCH * NKV * SEQ * HD];
__device__ __half        g_vf16[BATCH * NKV * SEQ * HD];

// ---------------------------------------------------------------------------
// PTX helpers
// ---------------------------------------------------------------------------
__device__ __forceinline__ uint32_t smem_u32(const void* p) {
    uint32_t a;
    asm("{ .reg .u64 t; cvta.to.shared.u64 t, %1; cvt.u32.u64 %0, t; }"
        : "=r"(a) : "l"(p));
    return a;
}

#define CP_ASYNC16(dst, src) \
    asm volatile("cp.async.cg.shared.global [%0], [%1], 16;" :: "r"(dst), "l"(src) : "memory")
#define CP_COMMIT() asm volatile("cp.async.commit_group;" ::: "memory")
#define CP_WAIT0()  asm volatile("cp.async.wait_group 0;" ::: "memory")
#define CP_WAIT1()  asm volatile("cp.async.wait_group 1;" ::: "memory")
#define CP_WAIT2()  asm volatile("cp.async.wait_group 2;" ::: "memory")

__device__ __forceinline__ void ldsm4(uint32_t* r, uint32_t addr) {
    asm volatile("ldmatrix.sync.aligned.m8n8.x4.shared.b16 {%0,%1,%2,%3}, [%4];"
        : "=r"(r[0]), "=r"(r[1]), "=r"(r[2]), "=r"(r[3]) : "r"(addr));
}
__device__ __forceinline__ void ldsm4t(uint32_t* r, uint32_t addr) {
    asm volatile("ldmatrix.sync.aligned.m8n8.x4.trans.shared.b16 {%0,%1,%2,%3}, [%4];"
        : "=r"(r[0]), "=r"(r[1]), "=r"(r[2]), "=r"(r[3]) : "r"(addr));
}

// bf16 mma (flash QK)
__device__ __forceinline__ void mma_bf(float* d, const uint32_t* a, const uint32_t* b) {
    asm volatile(
        "mma.sync.aligned.m16n8k16.row.col.f32.bf16.bf16.f32 "
        "{%0,%1,%2,%3}, {%4,%5,%6,%7}, {%8,%9}, {%0,%1,%2,%3};"
        : "+f"(d[0]), "+f"(d[1]), "+f"(d[2]), "+f"(d[3])
        : "r"(a[0]), "r"(a[1]), "r"(a[2]), "r"(a[3]), "r"(b[0]), "r"(b[1]));
}
// fp16 mma (GEMMs + flash PV)
__device__ __forceinline__ void mma_hf(float* d, const uint32_t* a, const uint32_t* b) {
    asm volatile(
        "mma.sync.aligned.m16n8k16.row.col.f32.f16.f16.f32 "
        "{%0,%1,%2,%3}, {%4,%5,%6,%7}, {%8,%9}, {%0,%1,%2,%3};"
        : "+f"(d[0]), "+f"(d[1]), "+f"(d[2]), "+f"(d[3])
        : "r"(a[0]), "r"(a[1]), "r"(a[2]), "r"(a[3]), "r"(b[0]), "r"(b[1]));
}

__device__ __forceinline__ uint32_t sw64(uint32_t off) {
    return off ^ ((off >> 3) & 0x30);
}

__device__ __forceinline__ uint32_t packbf(float lo, float hi) {
    uint32_t r;
    asm("cvt.rn.bf16x2.f32 %0, %1, %2;" : "=r"(r) : "f"(hi), "f"(lo));
    return r;
}
__device__ __forceinline__ uint32_t packhf(float lo, float hi) {
    uint32_t r;
    asm("cvt.rn.f16x2.f32 %0, %1, %2;" : "=r"(r) : "f"(hi), "f"(lo));
    return r;
}

__device__ __forceinline__ float ex2(float x) {
    float r;
    asm("ex2.approx.f32 %0, %1;" : "=f"(r) : "f"(x));
    return r;
}

// ---------------------------------------------------------------------------
// Prep kernels
// ---------------------------------------------------------------------------
// plain fp32 -> fp16 convert (vec4)
__global__ void cvt16_kernel(const float* __restrict__ in,
                             __half* __restrict__ out, int n)
{
    int i = (blockIdx.x * blockDim.x + threadIdx.x) * 4;
    if (i >= n) return;
    float4 v = *(const float4*)(in + i);
    uint32_t p0 = packhf(v.x, v.y);
    uint32_t p1 = packhf(v.z, v.w);
    *(uint2*)(out + i) = make_uint2(p0, p1);
}

// Merged transpose+split (fp16 hi/lo) for all 4 weights. in [4096,N] -> [N,4096].
__global__ void splitW_kernel(
    const float* __restrict__ wq, const float* __restrict__ wk,
    const float* __restrict__ wv, const float* __restrict__ wo,
    __half* __restrict__ qh, __half* __restrict__ ql,
    __half* __restrict__ kh, __half* __restrict__ kl,
    __half* __restrict__ vh, __half* __restrict__ vl,
    __half* __restrict__ oh, __half* __restrict__ ol)
{
    const int z = blockIdx.z;
    const float* in;
    __half *hi, *lo;
    int N;
    if (z == 0)      { in = wq; hi = qh; lo = ql; N = 4096; }
    else if (z == 1) { in = wk; hi = kh; lo = kl; N = 1024; }
    else if (z == 2) { in = wv; hi = vh; lo = vl; N = 1024; }
    else             { in = wo; hi = oh; lo = ol; N = 4096; }
    const int n0 = blockIdx.x * 32;
    if (n0 >= N) return;
    const int K = 4096;
    const int k0 = blockIdx.y * 32;

    __shared__ float t[32][33];
    const int tx = threadIdx.x, ty = threadIdx.y;
    for (int i = ty; i < 32; i += 8)
        t[i][tx] = in[(size_t)(k0 + i) * N + n0 + tx];
    __syncthreads();
    for (int i = ty; i < 32; i += 8) {
        float a = t[tx][i];
        __half h = __float2half_rn(a);
        __half l = __float2half_rn(a - __half2float(h));
        size_t o = (size_t)(n0 + i) * K + k0 + tx;
        hi[o] = h;
        lo[o] = l;
    }
}

// RoPE + scale + bf16 split (flash Q/K)
__global__ void rope_split(const float* __restrict__ x,
                           const float* __restrict__ cosb,
                           const float* __restrict__ sinb,
                           __nv_bfloat16* __restrict__ hi,
                           __nv_bfloat16* __restrict__ lo,
                           int nh, int total, float scale)
{
    int idx = blockIdx.x * blockDim.x + threadIdx.x;
    if (idx >= total) return;
    const int d = idx & 63;
    const int row = idx >> 6;
    const int s = row & (SEQ - 1);
    const int b = (row / SEQ) / nh;
    const float* xr = x + (size_t)row * HD;
    const float* cb = cosb + ((size_t)b * SEQ + s) * HD;
    const float* sb = sinb + ((size_t)b * SEQ + s) * HD;
    const float x0 = xr[d];
    const float x1 = xr[d + 64];
    const float y0 = (x0 * cb[d]      - x1 * sb[d])      * scale;
    const float y1 = (x1 * cb[d + 64] + x0 * sb[d + 64]) * scale;
    const size_t o = (size_t)row * HD + d;
    __nv_bfloat16 h0 = __float2bfloat16(y0);
    __nv_bfloat16 h1 = __float2bfloat16(y1);
    hi[o]      = h0;
    hi[o + 64] = h1;
    lo[o]      = __float2bfloat16(y0 - __bfloat162float(h0));
    lo[o + 64] = __float2bfloat16(y1 - __bfloat162float(h1));
}

// ---------------------------------------------------------------------------
// fp16 2-pass GEMM: C = A[fp16] @ (Bhi + Blo)^T. BM=BN=128, BK=32, 256 thr.
// Stage = [A 8KB][Bhi 8KB][Blo 8KB] = 24KB; 3 stages.
// MODE 0: row-major out. MODE 1: QKV scatter.
// ---------------------------------------------------------------------------
#define GT_SMEM (3 * 24576)

template <int MODE>
__global__ __launch_bounds__(256, 2) void gemm_hf(
    const __half* __restrict__ A,
    const __half* __restrict__ Bhi, const __half* __restrict__ Blo,
    float* __restrict__ C, int M, int N, int K, int nh)
{
    extern __shared__ char dsm[];
    const uint32_t sm_base = smem_u32(dsm);

    const int tid = threadIdx.x;
    const int wid = tid >> 5;
    const int lane = tid & 31;
    const int wm = wid & 3;
    const int wn = wid >> 2;
    const int m0 = blockIdx.y * 128;
    const int n0 = blockIdx.x * 128;

    const __half* srcs[3] = {A, Bhi, Blo};

    auto load_chunk = [&](int stage, int c) {
        const int k0 = c << 5;
        const uint32_t stb = sm_base + stage * 24576u;
#pragma unroll
        for (int it = 0; it < 6; it++) {
            int g = tid + it * 256;
            int arr = g >> 9;
            int rem = g & 511;
            int r = rem >> 2;
            int cg = rem & 3;
            int rowg = (arr == 0 ? m0 : n0) + r;
            const __half* src = srcs[arr] + (size_t)rowg * K + k0 + cg * 8;
            uint32_t off = sw64((uint32_t)(r * 64 + cg * 16));
            CP_ASYNC16(stb + arr * 8192u + off, src);
        }
        CP_COMMIT();
    };

    float acc[2][8][4];
#pragma unroll
    for (int mt = 0; mt < 2; mt++)
#pragma unroll
        for (int nt = 0; nt < 8; nt++)
#pragma unroll
            for (int i = 0; i < 4; i++) acc[mt][nt][i] = 0.f;

    const int NC = K >> 5;
    load_chunk(0, 0);
    load_chunk(1, 1);

    const uint32_t a_row = wm * 32 + (lane & 15);
    const uint32_t a_c16 = (lane >> 4);
    const uint32_t b_row = wn * 64 + ((lane >> 4) & 1) * 8 + (lane & 7);
    const uint32_t b_c16 = (lane >> 3) & 1;

    for (int c = 0; c < NC; c++) {
        if (c + 2 < NC) {
            load_chunk((c + 2) % 3, c + 2);
            CP_WAIT2();
        } else {
            CP_WAIT0();
        }
        __syncthreads();

        const uint32_t stb = sm_base + (uint32_t)(c % 3) * 24576u;
        const uint32_t Ab = stb, Bh = stb + 8192u, Bl = stb + 16384u;

#pragma unroll
        for (int kt = 0; kt < 2; kt++) {
            uint32_t af[2][4], bhf[4][4], blf[4][4];
#pragma unroll
            for (int mt = 0; mt < 2; mt++) {
                uint32_t off = sw64((a_row + mt * 16) * 64 + kt * 32 + a_c16 * 16);
                ldsm4(af[mt], Ab + off);
            }
#pragma unroll
            for (int p = 0; p < 4; p++) {
                uint32_t off = sw64((b_row + p * 16) * 64 + kt * 32 + b_c16 * 16);
                ldsm4(bhf[p], Bh + off);
                ldsm4(blf[p], Bl + off);
            }
#pragma unroll
            for (int mt = 0; mt < 2; mt++)
#pragma unroll
                for (int nt = 0; nt < 8; nt++)
                    mma_hf(acc[mt][nt], af[mt], &bhf[nt >> 1][(nt & 1) * 2]);
#pragma unroll
            for (int mt = 0; mt < 2; mt++)
#pragma unroll
                for (int nt = 0; nt < 8; nt++)
                    mma_hf(acc[mt][nt], af[mt], &blf[nt >> 1][(nt & 1) * 2]);
        }
        __syncthreads();
    }

    const int mr = m0 + wm * 32 + (lane >> 2);
    const int nc = n0 + wn * 64 + (lane & 3) * 2;
#pragma unroll
    for (int mt = 0; mt < 2; mt++) {
#pragma unroll
        for (int nt = 0; nt < 8; nt++) {
#pragma unroll
            for (int half = 0; half < 2; half++) {
                const int m = mr + mt * 16 + half * 8;
                const int n = nc + nt * 8;
                float2 v = make_float2(acc[mt][nt][half * 2], acc[mt][nt][half * 2 + 1]);
                if (MODE == 0) {
                    *(float2*)&C[(size_t)m * N + n] = v;
                } else {
                    const int b = m >> 11;
                    const int s = m & (SEQ - 1);
                    const int h = n >> 7;
                    const int d = n & (HD - 1);
                    *(float2*)&C[((size_t)(b * nh + h) * SEQ + s) * HD + d] = v;
                }
            }
        }
    }
}

// ---------------------------------------------------------------------------
// Flash attention v4: Br=128, Bc=64, 256 threads.
// QK: bf16 3-pass (pipelined ahead of softmax). PV: fp16 single-pass.
// Q 64KB + K ring 2x32KB + V ring 2x16KB = 160KB.
// Epilogue writes attn as fp16 single [b,s,h,d].
// ---------------------------------------------------------------------------
#define FLB_SMEM (65536 + 65536 + 32768)
#define NQT (SEQ / 128)   // 16

__global__ __launch_bounds__(256) void flash_mma(
    const __nv_bfloat16* __restrict__ Qhi, const __nv_bfloat16* __restrict__ Qlo,
    const __nv_bfloat16* __restrict__ Khi, const __nv_bfloat16* __restrict__ Klo,
    const __half* __restrict__ Vf,
    __half* __restrict__ Oa)
{
    extern __shared__ char dsm[];
    const uint32_t smQ = smem_u32(dsm);
    const uint32_t smK = smQ + 65536u;       // 2 stages x 32KB
    const uint32_t smV = smK + 65536u;       // 2 stages x 16KB

    const int tid = threadIdx.x;
    const int w = tid >> 5;
    const int lane = tid & 31;
    const int qt = NQT - 1 - blockIdx.x;     // longest first
    const int bh = blockIdx.y;
    const int b = bh / NHEADS;
    const int h = bh % NHEADS;
    const int kvh = h / NREP;
    const int q0 = qt * 128;

    const size_t qoff = ((size_t)(b * NHEADS + h) * SEQ + q0) * HD;
    const size_t kvbase = (size_t)(b * NKV + kvh) * SEQ * HD;

    auto load_K = [&](int stage, int kt) {
        const int k0 = kt * 64;
        const uint32_t stb = smK + stage * 32768u;
#pragma unroll
        for (int it = 0; it < 8; it++) {
            int g = tid + it * 256;
            int arr = g >> 10;
            int rem = g & 1023;
            int r = rem >> 4;
            int gg = rem & 15;
            const __nv_bfloat16* src = (arr ? Klo : Khi) + kvbase + (size_t)(k0 + r) * HD + gg * 8;
            uint32_t dst = stb + arr * 16384u + (gg >> 2) * 4096u
                         + sw64((uint32_t)(r * 64 + (gg & 3) * 16));
            CP_ASYNC16(dst, src);
        }
    };
    auto load_V = [&](int stage, int kt) {
        const int k0 = kt * 64;
        const uint32_t stb = smV + stage * 16384u;
#pragma unroll
        for (int it = 0; it < 4; it++) {
            int g = tid + it * 256;     // 1024 granules: 64 rows x 16
            int r = g >> 4;
            int gg = g & 15;
            const __half* src = Vf + kvbase + (size_t)(k0 + r) * HD + gg * 8;
            uint32_t dst = stb + (gg >> 2) * 4096u
                         + sw64((uint32_t)(r * 64 + (gg & 3) * 16));
            CP_ASYNC16(dst, src);
        }
    };

    // prologue: group A = {Q, K0}; group B = {K1, V0}
    {
#pragma unroll
        for (int it = 0; it < 16; it++) {
            int g = tid + it * 256;
            int arr = g >> 11;
            int rem = g & 2047;
            int r = rem >> 4;
            int gg = rem & 15;
            const __nv_bfloat16* src = (arr ? Qlo : Qhi) + qoff + (size_t)r * HD + gg * 8;
            uint32_t dst = smQ + arr * 32768u + (gg >> 2) * 8192u
                         + sw64((uint32_t)(r * 64 + (gg & 3) * 16));
            CP_ASYNC16(dst, src);
        }
    }
    load_K(0, 0);
    CP_COMMIT();
    const int nkt = 2 * qt + 2;
    if (nkt > 1) load_K(1, 1);
    load_V(0, 0);
    CP_COMMIT();

    float o[16][4];
#pragma unroll
    for (int nt = 0; nt < 16; nt++)
#pragma unroll
        for (int e = 0; e < 4; e++) o[nt][e] = 0.f;
    float m_prev[2] = {NEG_BIG, NEG_BIG};
    float l[2] = {0.f, 0.f};

    const uint32_t a_row = w * 16 + (lane & 15);
    const uint32_t a_c16 = (lane >> 4) * 16;
    const uint32_t b_row = ((lane >> 4) & 1) * 8 + (lane & 7);
    const uint32_t b_c16 = ((lane >> 3) & 1) * 16;
    const uint32_t v_row = (lane & 7) + ((lane >> 3) & 1) * 8;
    const uint32_t v_c16 = (lane >> 4) * 16;

    float sA[8][4], sB[8][4];

    auto do_qk = [&](int kt, float (*sn)[4]) {
        const uint32_t Kst = smK + (uint32_t)(kt & 1) * 32768u;
        const uint32_t Kh = Kst, Kl = Kst + 16384u;
#pragma unroll
        for (int j = 0; j < 8; j++)
#pragma unroll
            for (int e = 0; e < 4; e++) sn[j][e] = 0.f;
#pragma unroll
        for (int ks = 0; ks < 8; ks++) {
            const uint32_t qoffb = (ks >> 1) * 8192u
                + sw64(a_row * 64 + (ks & 1) * 32 + a_c16);
            uint32_t qh[4], ql[4];
            ldsm4(qh, smQ + qoffb);
            ldsm4(ql, smQ + 32768u + qoffb);
            uint32_t kh[4][4], klf[4][4];
#pragma unroll
            for (int p = 0; p < 4; p++) {
                const uint32_t koffb = (ks >> 1) * 4096u
                    + sw64((b_row + p * 16) * 64 + (ks & 1) * 32 + b_c16);
                ldsm4(kh[p], Kh + koffb);
                ldsm4(klf[p], Kl + koffb);
            }
#pragma unroll
            for (int j = 0; j < 8; j++)
                mma_bf(sn[j], qh, &kh[j >> 1][(j & 1) * 2]);
#pragma unroll
            for (int j = 0; j < 8; j++)
                mma_bf(sn[j], qh, &klf[j >> 1][(j & 1) * 2]);
#pragma unroll
            for (int j = 0; j < 8; j++)
                mma_bf(sn[j], ql, &kh[j >> 1][(j & 1) * 2]);
        }
    };

    auto do_softmax_pv = [&](int kt, float (*s)[4]) {
        const bool diag = (kt >= nkt - 2);
        if (diag) {
            const int k0 = kt * 64;
#pragma unroll
            for (int j = 0; j < 8; j++)
#pragma unroll
                for (int e = 0; e < 4; e++) {
                    const int cglob = k0 + j * 8 + (lane & 3) * 2 + (e & 1);
                    const int rglob = q0 + w * 16 + (lane >> 2) + (e >> 1) * 8;
                    if (cglob > rglob) s[j][e] = NEG_BIG;
                }
        }

        float mx0 = NEG_BIG, mx1 = NEG_BIG;
#pragma unroll
        for (int j = 0; j < 8; j++) {
            mx0 = fmaxf(mx0, fmaxf(s[j][0], s[j][1]));
            mx1 = fmaxf(mx1, fmaxf(s[j][2], s[j][3]));
        }
        mx0 = fmaxf(mx0, __shfl_xor_sync(0xffffffffu, mx0, 1));
        mx0 = fmaxf(mx0, __shfl_xor_sync(0xffffffffu, mx0, 2));
        mx1 = fmaxf(mx1, __shfl_xor_sync(0xffffffffu, mx1, 1));
        mx1 = fmaxf(mx1, __shfl_xor_sync(0xffffffffu, mx1, 2));

        const float mn0 = fmaxf(m_prev[0], mx0);
        const float mn1 = fmaxf(m_prev[1], mx1);
        const float corr0 = ex2(m_prev[0] - mn0);
        const float corr1 = ex2(m_prev[1] - mn1);
        m_prev[0] = mn0;
        m_prev[1] = mn1;

        float rs0 = 0.f, rs1 = 0.f;
#pragma unroll
        for (int j = 0; j < 8; j++) {
            s[j][0] = ex2(s[j][0] - mn0);
            s[j][1] = ex2(s[j][1] - mn0);
            s[j][2] = ex2(s[j][2] - mn1);
            s[j][3] = ex2(s[j][3] - mn1);
            rs0 += s[j][0] + s[j][1];
            rs1 += s[j][2] + s[j][3];
        }
        rs0 += __shfl_xor_sync(0xffffffffu, rs0, 1);
        rs0 += __shfl_xor_sync(0xffffffffu, rs0, 2);
        rs1 += __shfl_xor_sync(0xffffffffu, rs1, 1);
        rs1 += __shfl_xor_sync(0xffffffffu, rs1, 2);
        l[0] = l[0] * corr0 + rs0;
        l[1] = l[1] * corr1 + rs1;

#pragma unroll
        for (int nt = 0; nt < 16; nt++) {
            o[nt][0] *= corr0; o[nt][1] *= corr0;
            o[nt][2] *= corr1; o[nt][3] *= corr1;
        }

        const uint32_t Vst = smV + (uint32_t)(kt & 1) * 16384u;
#pragma unroll
        for (int ks = 0; ks < 4; ks++) {
            // pack P chunk (rows 2ks, 2ks+1) single fp16
            const int j0 = 2 * ks, j1 = 2 * ks + 1;
            uint32_t pf[4];
            pf[0] = packhf(s[j0][0], s[j0][1]);
            pf[1] = packhf(s[j0][2], s[j0][3]);
            pf[2] = packhf(s[j1][0], s[j1][1]);
            pf[3] = packhf(s[j1][2], s[j1][3]);
#pragma unroll
            for (int c = 0; c < 4; c++) {
                uint32_t vh0[4], vh1[4];
                const uint32_t vb0 = c * 4096u + sw64((ks * 16 + v_row) * 64 + v_c16);
                const uint32_t vb1 = c * 4096u + sw64((ks * 16 + v_row) * 64 + 32 + v_c16);
                ldsm4t(vh0, Vst + vb0);
                ldsm4t(vh1, Vst + vb1);
                mma_hf(o[c * 4 + 0], pf, vh0 + 0);
                mma_hf(o[c * 4 + 1], pf, vh0 + 2);
                mma_hf(o[c * 4 + 2], pf, vh1 + 0);
                mma_hf(o[c * 4 + 3], pf, vh1 + 2);
            }
        }
    };

    CP_WAIT1();
    __syncthreads();
    do_qk(0, sA);

    auto body = [&](int i, float (*scur)[4], float (*snxt)[4]) {
        CP_WAIT0();
        __syncthreads();
        if (i + 1 < nkt) load_V((i + 1) & 1, i + 1);
        if (i + 2 < nkt) load_K((i + 2) & 1, i + 2);
        CP_COMMIT();
        if (i + 1 < nkt) do_qk(i + 1, snxt);
        do_softmax_pv(i, scur);
    };

    for (int i = 0; i < nkt; i += 2) {
        body(i, sA, sB);
        if (i + 1 < nkt) body(i + 1, sB, sA);
    }

    // epilogue: write attn fp16 [b,s,h,d]
    const float inv0 = 1.f / l[0];
    const float inv1 = 1.f / l[1];
    const int row0 = q0 + w * 16 + (lane >> 2);
#pragma unroll
    for (int nt = 0; nt < 16; nt++) {
        const int d = nt * 8 + (lane & 3) * 2;
        const size_t o0 = ((size_t)(b * SEQ + row0) * NHEADS + h) * HD + d;
        const size_t o1 = ((size_t)(b * SEQ + row0 + 8) * NHEADS + h) * HD + d;
        *(uint32_t*)&Oa[o0] = packhf(o[nt][0] * inv0, o[nt][1] * inv0);
        *(uint32_t*)&Oa[o1] = packhf(o[nt][2] * inv1, o[nt][3] * inv1);
    }
}

// ---------------------------------------------------------------------------
extern "C" void kernel_launch(void* const* d_in, const int* in_sizes, int n_in,
                              void* d_out, int out_size)
{
    const float* X    = (const float*)d_in[0];
    const float* cosb = (const float*)d_in[1];
    const float* sinb = (const float*)d_in[2];
    const float* wq = (const float*)d_in[4];
    const float* wk = (const float*)d_in[5];
    const float* wv = (const float*)d_in[6];
    const float* wo = (const float*)d_in[7];
    float* out = (float*)d_out;

    void *pq, *pk, *pv;
    cudaGetSymbolAddress(&pq, g_q);
    cudaGetSymbolAddress(&pk, g_k);
    cudaGetSymbolAddress(&pv, g_v);
    float* Qb = (float*)pq;
    float* Kb = (float*)pk;
    float* Vb = (float*)pv;

    void *pxf, *pqh, *pql, *pkh, *pkl, *pvh, *pvl, *poh, *pol, *paf, *pvf;
    cudaGetSymbolAddress(&pxf, g_xf16);
    cudaGetSymbolAddress(&pqh, g_wqT_hi); cudaGetSymbolAddress(&pql, g_wqT_lo);
    cudaGetSymbolAddress(&pkh, g_wkT_hi); cudaGetSymbolAddress(&pkl, g_wkT_lo);
    cudaGetSymbolAddress(&pvh, g_wvT_hi); cudaGetSymbolAddress(&pvl, g_wvT_lo);
    cudaGetSymbolAddress(&poh, g_woT_hi); cudaGetSymbolAddress(&pol, g_woT_lo);
    cudaGetSymbolAddress(&paf, g_af16);
    cudaGetSymbolAddress(&pvf, g_vf16);
    __half *Xf = (__half*)pxf;
    __half *WqHi = (__half*)pqh, *WqLo = (__half*)pql;
    __half *WkHi = (__half*)pkh, *WkLo = (__half*)pkl;
    __half *WvHi = (__half*)pvh, *WvLo = (__half*)pvl;
    __half *WoHi = (__half*)poh, *WoLo = (__half*)pol;
    __half *Af = (__half*)paf;
    __half *Vf = (__half*)pvf;

    void *pfqh, *pfql, *pfkh, *pfkl;
    cudaGetSymbolAddress(&pfqh, g_qhi); cudaGetSymbolAddress(&pfql, g_qlo);
    cudaGetSymbolAddress(&pfkh, g_khi); cudaGetSymbolAddress(&pfkl, g_klo);
    __nv_bfloat16 *FQh = (__nv_bfloat16*)pfqh, *FQl = (__nv_bfloat16*)pfql;
    __nv_bfloat16 *FKh = (__nv_bfloat16*)pfkh, *FKl = (__nv_bfloat16*)pfkl;

    static bool attr_set = false;
    if (!attr_set) {
        cudaFuncSetAttribute(gemm_hf<0>, cudaFuncAttributeMaxDynamicSharedMemorySize, GT_SMEM);
        cudaFuncSetAttribute(gemm_hf<1>, cudaFuncAttributeMaxDynamicSharedMemorySize, GT_SMEM);
        cudaFuncSetAttribute(flash_mma, cudaFuncAttributeMaxDynamicSharedMemorySize, FLB_SMEM);
        attr_set = true;
    }

    const int M = BATCH * SEQ;   // 4096

    // prep: X -> fp16; weights -> fp16 hi/lo transposed
    cvt16_kernel<<<(M * HID / 4 + 255) / 256, 256>>>(X, Xf, M * HID);
    splitW_kernel<<<dim3(128, 128, 4), dim3(32, 8)>>>(
        wq, wk, wv, wo, WqHi, WqLo, WkHi, WkLo, WvHi, WvLo, WoHi, WoLo);

    // projections (fp16 2-pass)
    gemm_hf<1><<<dim3(32, 32), 256, GT_SMEM>>>(Xf, WqHi, WqLo, Qb, M, 4096, HID, NHEADS);
    gemm_hf<1><<<dim3(8, 32), 256, GT_SMEM>>>(Xf, WkHi, WkLo, Kb, M, 1024, HID, NKV);
    gemm_hf<1><<<dim3(8, 32), 256, GT_SMEM>>>(Xf, WvHi, WvLo, Vb, M, 1024, HID, NKV);

    // RoPE + bf16 split for Q/K; fp16 convert for V
    {
        int totq = BATCH * NHEADS * SEQ * 64;
        rope_split<<<(totq + 255) / 256, 256>>>(Qb, cosb, sinb, FQh, FQl, NHEADS, totq, QSCALE);
        int totk = BATCH * NKV * SEQ * 64;
        rope_split<<<(totk + 255) / 256, 256>>>(Kb, cosb, sinb, FKh, FKl, NKV, totk, 1.0f);
        int nkv = BATCH * NKV * SEQ * HD;
        cvt16_kernel<<<(nkv / 4 + 255) / 256, 256>>>(Vb, Vf, nkv);
    }

    // flash attention -> attn fp16 [b,s,h,d]
    flash_mma<<<dim3(NQT, BATCH * NHEADS), 256, FLB_SMEM>>>(
        FQh, FQl, FKh, FKl, Vf, Af);

    // output projection (fp16 2-pass)
    gemm_hf<0><<<dim3(32, 32), 256, GT_SMEM>>>(Af, WoHi, WoLo, out, M, HID, 4096, 0);

    (void)in_sizes; (void)n_in; (void)out_size;
}

// round 10
// speedup vs baseline: 1.6976x; 1.0576x over previous
#include <cuda_runtime.h>
#include <cuda_bf16.h>
#include <cuda_fp16.h>
#include <math.h>
#include <stdint.h>

// Problem constants
#define BATCH   2
#define SEQ     2048
#define HID     4096
#define NHEADS  32
#define NKV     8
#define NREP    4
#define HD      128
#define SCALING 0.08838834764831845f           // 128^-0.5
#define QSCALE  0.1275429555686623f            // SCALING * log2(e)
#define NEG_BIG (-1.0e30f)

// ---------------------------------------------------------------------------
// Scratch (device globals)
// ---------------------------------------------------------------------------
__device__ float g_q[BATCH * NHEADS * SEQ * HD];
__device__ float g_k[BATCH * NKV * SEQ * HD];
__device__ float g_v[BATCH * NKV * SEQ * HD];

// fp16 GEMM operands
__device__ __half g_xf16[4096 * 4096];
__device__ __half g_wqkvT_hi[6144 * 4096], g_wqkvT_lo[6144 * 4096];  // merged QKV weights [N,K]
__device__ __half g_woT_hi[4096 * 4096], g_woT_lo[4096 * 4096];
__device__ __half g_af16[4096 * 4096];        // attn output (fp16 single)

// flash operands: Q/K bf16 hi/lo (3-pass QK), V fp16 single
__device__ __nv_bfloat16 g_qhi[BATCH * NHEADS * SEQ * HD], g_qlo[BATCH * NHEADS * SEQ * HD];
__device__ __nv_bfloat16 g_khi[BATCH * NKV * SEQ * HD],    g_klo[BATCH * NKV * SEQ * HD];
__device__ __half        g_vf16[BATCH * NKV * SEQ * HD];

// ---------------------------------------------------------------------------
// PTX helpers
// ---------------------------------------------------------------------------
__device__ __forceinline__ uint32_t smem_u32(const void* p) {
    uint32_t a;
    asm("{ .reg .u64 t; cvta.to.shared.u64 t, %1; cvt.u32.u64 %0, t; }"
        : "=r"(a) : "l"(p));
    return a;
}

#define CP_ASYNC16(dst, src) \
    asm volatile("cp.async.cg.shared.global [%0], [%1], 16;" :: "r"(dst), "l"(src) : "memory")
#define CP_COMMIT() asm volatile("cp.async.commit_group;" ::: "memory")
#define CP_WAIT0()  asm volatile("cp.async.wait_group 0;" ::: "memory")
#define CP_WAIT1()  asm volatile("cp.async.wait_group 1;" ::: "memory")

__device__ __forceinline__ void ldsm4(uint32_t* r, uint32_t addr) {
    asm volatile("ldmatrix.sync.aligned.m8n8.x4.shared.b16 {%0,%1,%2,%3}, [%4];"
        : "=r"(r[0]), "=r"(r[1]), "=r"(r[2]), "=r"(r[3]) : "r"(addr));
}
__device__ __forceinline__ void ldsm4t(uint32_t* r, uint32_t addr) {
    asm volatile("ldmatrix.sync.aligned.m8n8.x4.trans.shared.b16 {%0,%1,%2,%3}, [%4];"
        : "=r"(r[0]), "=r"(r[1]), "=r"(r[2]), "=r"(r[3]) : "r"(addr));
}

__device__ __forceinline__ void mma_bf(float* d, const uint32_t* a, const uint32_t* b) {
    asm volatile(
        "mma.sync.aligned.m16n8k16.row.col.f32.bf16.bf16.f32 "
        "{%0,%1,%2,%3}, {%4,%5,%6,%7}, {%8,%9}, {%0,%1,%2,%3};"
        : "+f"(d[0]), "+f"(d[1]), "+f"(d[2]), "+f"(d[3])
        : "r"(a[0]), "r"(a[1]), "r"(a[2]), "r"(a[3]), "r"(b[0]), "r"(b[1]));
}
__device__ __forceinline__ void mma_hf(float* d, const uint32_t* a, const uint32_t* b) {
    asm volatile(
        "mma.sync.aligned.m16n8k16.row.col.f32.f16.f16.f32 "
        "{%0,%1,%2,%3}, {%4,%5,%6,%7}, {%8,%9}, {%0,%1,%2,%3};"
        : "+f"(d[0]), "+f"(d[1]), "+f"(d[2]), "+f"(d[3])
        : "r"(a[0]), "r"(a[1]), "r"(a[2]), "r"(a[3]), "r"(b[0]), "r"(b[1]));
}

__device__ __forceinline__ uint32_t sw64(uint32_t off) {
    return off ^ ((off >> 3) & 0x30);
}
__device__ __forceinline__ uint32_t sw128(uint32_t off) {
    return off ^ ((off >> 3) & 0x70);
}

__device__ __forceinline__ uint32_t packhf(float lo, float hi) {
    uint32_t r;
    asm("cvt.rn.f16x2.f32 %0, %1, %2;" : "=r"(r) : "f"(hi), "f"(lo));
    return r;
}

__device__ __forceinline__ float ex2(float x) {
    float r;
    asm("ex2.approx.f32 %0, %1;" : "=f"(r) : "f"(x));
    return r;
}

// ---------------------------------------------------------------------------
// Prep kernels
// ---------------------------------------------------------------------------
__global__ void cvt16_kernel(const float* __restrict__ in,
                             __half* __restrict__ out, int n)
{
    int i = (blockIdx.x * blockDim.x + threadIdx.x) * 4;
    if (i >= n) return;
    float4 v = *(const float4*)(in + i);
    uint32_t p0 = packhf(v.x, v.y);
    uint32_t p1 = packhf(v.z, v.w);
    *(uint2*)(out + i) = make_uint2(p0, p1);
}

// Merged transpose+split (fp16 hi/lo): wq/wk/wv -> one [6144,4096] buffer, wo separate.
__global__ void splitW_kernel(
    const float* __restrict__ wq, const float* __restrict__ wk,
    const float* __restrict__ wv, const float* __restrict__ wo,
    __half* __restrict__ qkvh, __half* __restrict__ qkvl,
    __half* __restrict__ oh, __half* __restrict__ ol)
{
    const int z = blockIdx.z;
    const float* in;
    __half *hi, *lo;
    int N, rbase;
    if (z == 0)      { in = wq; hi = qkvh; lo = qkvl; N = 4096; rbase = 0; }
    else if (z == 1) { in = wk; hi = qkvh; lo = qkvl; N = 1024; rbase = 4096; }
    else if (z == 2) { in = wv; hi = qkvh; lo = qkvl; N = 1024; rbase = 5120; }
    else             { in = wo; hi = oh;   lo = ol;   N = 4096; rbase = 0; }
    const int n0 = blockIdx.x * 32;
    if (n0 >= N) return;
    const int K = 4096;
    const int k0 = blockIdx.y * 32;

    __shared__ float t[32][33];
    const int tx = threadIdx.x, ty = threadIdx.y;
    for (int i = ty; i < 32; i += 8)
        t[i][tx] = in[(size_t)(k0 + i) * N + n0 + tx];
    __syncthreads();
    for (int i = ty; i < 32; i += 8) {
        float a = t[tx][i];
        __half h = __float2half_rn(a);
        __half l = __float2half_rn(a - __half2float(h));
        size_t o = (size_t)(rbase + n0 + i) * K + k0 + tx;
        hi[o] = h;
        lo[o] = l;
    }
}

// All flash preps in one launch: rope+bf16split Q, rope+bf16split K, fp16 cvt V
#define PREP_QT (BATCH * NHEADS * SEQ * 64)        // 8388608
#define PREP_KT (BATCH * NKV * SEQ * 64)           // 2097152
#define PREP_VT (BATCH * NKV * SEQ * HD / 4)       // 1048576

__device__ __forceinline__ void rope_one(
    const float* __restrict__ x, const float* __restrict__ cosb,
    const float* __restrict__ sinb, __nv_bfloat16* __restrict__ hi,
    __nv_bfloat16* __restrict__ lo, int nh, float scale, int idx)
{
    const int d = idx & 63;
    const int row = idx >> 6;
    const int s = row & (SEQ - 1);
    const int b = (row / SEQ) / nh;
    const float* xr = x + (size_t)row * HD;
    const float* cb = cosb + ((size_t)b * SEQ + s) * HD;
    const float* sb = sinb + ((size_t)b * SEQ + s) * HD;
    const float x0 = xr[d];
    const float x1 = xr[d + 64];
    const float y0 = (x0 * cb[d]      - x1 * sb[d])      * scale;
    const float y1 = (x1 * cb[d + 64] + x0 * sb[d + 64]) * scale;
    const size_t o = (size_t)row * HD + d;
    __nv_bfloat16 h0 = __float2bfloat16(y0);
    __nv_bfloat16 h1 = __float2bfloat16(y1);
    hi[o]      = h0;
    hi[o + 64] = h1;
    lo[o]      = __float2bfloat16(y0 - __bfloat162float(h0));
    lo[o + 64] = __float2bfloat16(y1 - __bfloat162float(h1));
}

__global__ void prep_kernel(
    const float* __restrict__ Qb, const float* __restrict__ Kb,
    const float* __restrict__ Vb,
    const float* __restrict__ cosb, const float* __restrict__ sinb,
    __nv_bfloat16* __restrict__ FQh, __nv_bfloat16* __restrict__ FQl,
    __nv_bfloat16* __restrict__ FKh, __nv_bfloat16* __restrict__ FKl,
    __half* __restrict__ Vf)
{
    int idx = blockIdx.x * blockDim.x + threadIdx.x;
    if (idx < PREP_QT) {
        rope_one(Qb, cosb, sinb, FQh, FQl, NHEADS, QSCALE, idx);
    } else if (idx < PREP_QT + PREP_KT) {
        rope_one(Kb, cosb, sinb, FKh, FKl, NKV, 1.0f, idx - PREP_QT);
    } else if (idx < PREP_QT + PREP_KT + PREP_VT) {
        int i = (idx - PREP_QT - PREP_KT) * 4;
        float4 v = *(const float4*)(Vb + i);
        uint32_t p0 = packhf(v.x, v.y);
        uint32_t p1 = packhf(v.z, v.w);
        *(uint2*)(Vf + i) = make_uint2(p0, p1);
    }
}

// ---------------------------------------------------------------------------
// fp16 2-pass GEMM, BK=64: C = A[fp16] @ (Bhi + Blo)^T. BM=BN=128, 256 thr.
// Stage = [A 16KB][Bhi 16KB][Blo 16KB] = 48KB; 2 stages (96KB) -> 2 CTAs/SM.
// MODE 0: row-major out (Qo). MODE 1: merged-QKV scatter (Qo/Ko/Vo by n).
// ---------------------------------------------------------------------------
#define GT_SMEM (2 * 49152)

template <int MODE>
__global__ __launch_bounds__(256, 2) void gemm_hf(
    const __half* __restrict__ A,
    const __half* __restrict__ Bhi, const __half* __restrict__ Blo,
    float* __restrict__ Qo, float* __restrict__ Ko, float* __restrict__ Vo,
    int M, int N, int K)
{
    extern __shared__ char dsm[];
    const uint32_t sm_base = smem_u32(dsm);

    const int tid = threadIdx.x;
    const int wid = tid >> 5;
    const int lane = tid & 31;
    const int wm = wid & 3;
    const int wn = wid >> 2;
    const int m0 = blockIdx.y * 128;
    const int n0 = blockIdx.x * 128;

    const __half* srcs[3] = {A, Bhi, Blo};

    // stage: 3 arrays x 128 rows x 8 granules(16B) = 3072 granules
    auto load_chunk = [&](int stage, int c) {
        const int k0 = c << 6;
        const uint32_t stb = sm_base + stage * 49152u;
#pragma unroll
        for (int it = 0; it < 12; it++) {
            int g = tid + it * 256;
            int arr = g >> 10;
            int rem = g & 1023;
            int r = rem >> 3;
            int gg = rem & 7;
            int rowg = (arr == 0 ? m0 : n0) + r;
            const __half* src = srcs[arr] + (size_t)rowg * K + k0 + gg * 8;
            uint32_t off = sw128((uint32_t)(r * 128 + gg * 16));
            CP_ASYNC16(stb + arr * 16384u + off, src);
        }
        CP_COMMIT();
    };

    float acc[2][8][4];
#pragma unroll
    for (int mt = 0; mt < 2; mt++)
#pragma unroll
        for (int nt = 0; nt < 8; nt++)
#pragma unroll
            for (int i = 0; i < 4; i++) acc[mt][nt][i] = 0.f;

    const int NC = K >> 6;
    load_chunk(0, 0);

    const uint32_t a_row = wm * 32 + (lane & 15);
    const uint32_t a_c16 = (lane >> 4) * 16;
    const uint32_t b_row = wn * 64 + ((lane >> 4) & 1) * 8 + (lane & 7);
    const uint32_t b_c16 = ((lane >> 3) & 1) * 16;

    for (int c = 0; c < NC; c++) {
        if (c + 1 < NC) {
            load_chunk((c + 1) & 1, c + 1);
            CP_WAIT1();
        } else {
            CP_WAIT0();
        }
        __syncthreads();

        const uint32_t stb = sm_base + (uint32_t)(c & 1) * 49152u;
        const uint32_t Ab = stb, Bh = stb + 16384u, Bl = stb + 32768u;

#pragma unroll
        for (int kt = 0; kt < 4; kt++) {
            uint32_t af[2][4], bhf[4][4], blf[4][4];
#pragma unroll
            for (int mt = 0; mt < 2; mt++) {
                uint32_t off = sw128((a_row + mt * 16) * 128 + kt * 32 + a_c16);
                ldsm4(af[mt], Ab + off);
            }
#pragma unroll
            for (int p = 0; p < 4; p++) {
                uint32_t off = sw128((b_row + p * 16) * 128 + kt * 32 + b_c16);
                ldsm4(bhf[p], Bh + off);
                ldsm4(blf[p], Bl + off);
            }
#pragma unroll
            for (int mt = 0; mt < 2; mt++)
#pragma unroll
                for (int nt = 0; nt < 8; nt++)
                    mma_hf(acc[mt][nt], af[mt], &bhf[nt >> 1][(nt & 1) * 2]);
#pragma unroll
            for (int mt = 0; mt < 2; mt++)
#pragma unroll
                for (int nt = 0; nt < 8; nt++)
                    mma_hf(acc[mt][nt], af[mt], &blf[nt >> 1][(nt & 1) * 2]);
        }
        __syncthreads();
    }

    const int mr = m0 + wm * 32 + (lane >> 2);
    const int nc = n0 + wn * 64 + (lane & 3) * 2;
#pragma unroll
    for (int mt = 0; mt < 2; mt++) {
#pragma unroll
        for (int nt = 0; nt < 8; nt++) {
#pragma unroll
            for (int half = 0; half < 2; half++) {
                const int m = mr + mt * 16 + half * 8;
                const int n = nc + nt * 8;
                float2 v = make_float2(acc[mt][nt][half * 2], acc[mt][nt][half * 2 + 1]);
                if (MODE == 0) {
                    *(float2*)&Qo[(size_t)m * N + n] = v;
                } else {
                    const int b = m >> 11;
                    const int s = m & (SEQ - 1);
                    const int d = n & (HD - 1);
                    if (n < 4096) {
                        const int h = n >> 7;
                        *(float2*)&Qo[((size_t)(b * NHEADS + h) * SEQ + s) * HD + d] = v;
                    } else if (n < 5120) {
                        const int kv = (n - 4096) >> 7;
                        *(float2*)&Ko[((size_t)(b * NKV + kv) * SEQ + s) * HD + d] = v;
                    } else {
                        const int kv = (n - 5120) >> 7;
                        *(float2*)&Vo[((size_t)(b * NKV + kv) * SEQ + s) * HD + d] = v;
                    }
                }
            }
        }
    }
}

// ---------------------------------------------------------------------------
// Flash attention v4 (unchanged math): Br=128, Bc=64, 256 threads.
// QK bf16 3-pass pipelined; PV fp16 single. Split into 2 launches via bh_base.
// ---------------------------------------------------------------------------
#define FLB_SMEM (65536 + 65536 + 32768)
#define NQT (SEQ / 128)   // 16

__global__ __launch_bounds__(256) void flash_mma(
    const __nv_bfloat16* __restrict__ Qhi, const __nv_bfloat16* __restrict__ Qlo,
    const __nv_bfloat16* __restrict__ Khi, const __nv_bfloat16* __restrict__ Klo,
    const __half* __restrict__ Vf,
    __half* __restrict__ Oa, int bh_base)
{
    extern __shared__ char dsm[];
    const uint32_t smQ = smem_u32(dsm);
    const uint32_t smK = smQ + 65536u;
    const uint32_t smV = smK + 65536u;

    const int tid = threadIdx.x;
    const int w = tid >> 5;
    const int lane = tid & 31;
    const int qt = NQT - 1 - blockIdx.x;
    const int bh = bh_base + blockIdx.y;
    const int b = bh / NHEADS;
    const int h = bh % NHEADS;
    const int kvh = h / NREP;
    const int q0 = qt * 128;

    const size_t qoff = ((size_t)(b * NHEADS + h) * SEQ + q0) * HD;
    const size_t kvbase = (size_t)(b * NKV + kvh) * SEQ * HD;

    auto load_K = [&](int stage, int kt) {
        const int k0 = kt * 64;
        const uint32_t stb = smK + stage * 32768u;
#pragma unroll
        for (int it = 0; it < 8; it++) {
            int g = tid + it * 256;
            int arr = g >> 10;
            int rem = g & 1023;
            int r = rem >> 4;
            int gg = rem & 15;
            const __nv_bfloat16* src = (arr ? Klo : Khi) + kvbase + (size_t)(k0 + r) * HD + gg * 8;
            uint32_t dst = stb + arr * 16384u + (gg >> 2) * 4096u
                         + sw64((uint32_t)(r * 64 + (gg & 3) * 16));
            CP_ASYNC16(dst, src);
        }
    };
    auto load_V = [&](int stage, int kt) {
        const int k0 = kt * 64;
        const uint32_t stb = smV + stage * 16384u;
#pragma unroll
        for (int it = 0; it < 4; it++) {
            int g = tid + it * 256;
            int r = g >> 4;
            int gg = g & 15;
            const __half* src = Vf + kvbase + (size_t)(k0 + r) * HD + gg * 8;
            uint32_t dst = stb + (gg >> 2) * 4096u
                         + sw64((uint32_t)(r * 64 + (gg & 3) * 16));
            CP_ASYNC16(dst, src);
        }
    };

    {
#pragma unroll
        for (int it = 0; it < 16; it++) {
            int g = tid + it * 256;
            int arr = g >> 11;
            int rem = g & 2047;
            int r = rem >> 4;
            int gg = rem & 15;
            const __nv_bfloat16* src = (arr ? Qlo : Qhi) + qoff + (size_t)r * HD + gg * 8;
            uint32_t dst = smQ + arr * 32768u + (gg >> 2) * 8192u
                         + sw64((uint32_t)(r * 64 + (gg & 3) * 16));
            CP_ASYNC16(dst, src);
        }
    }
    load_K(0, 0);
    CP_COMMIT();
    const int nkt = 2 * qt + 2;
    if (nkt > 1) load_K(1, 1);
    load_V(0, 0);
    CP_COMMIT();

    float o[16][4];
#pragma unroll
    for (int nt = 0; nt < 16; nt++)
#pragma unroll
        for (int e = 0; e < 4; e++) o[nt][e] = 0.f;
    float m_prev[2] = {NEG_BIG, NEG_BIG};
    float l[2] = {0.f, 0.f};

    const uint32_t a_row = w * 16 + (lane & 15);
    const uint32_t a_c16 = (lane >> 4) * 16;
    const uint32_t b_row = ((lane >> 4) & 1) * 8 + (lane & 7);
    const uint32_t b_c16 = ((lane >> 3) & 1) * 16;
    const uint32_t v_row = (lane & 7) + ((lane >> 3) & 1) * 8;
    const uint32_t v_c16 = (lane >> 4) * 16;

    float sA[8][4], sB[8][4];

    auto do_qk = [&](int kt, float (*sn)[4]) {
        const uint32_t Kst = smK + (uint32_t)(kt & 1) * 32768u;
        const uint32_t Kh = Kst, Kl = Kst + 16384u;
#pragma unroll
        for (int j = 0; j < 8; j++)
#pragma unroll
            for (int e = 0; e < 4; e++) sn[j][e] = 0.f;
#pragma unroll
        for (int ks = 0; ks < 8; ks++) {
            const uint32_t qoffb = (ks >> 1) * 8192u
                + sw64(a_row * 64 + (ks & 1) * 32 + a_c16);
            uint32_t qh[4], ql[4];
            ldsm4(qh, smQ + qoffb);
            ldsm4(ql, smQ + 32768u + qoffb);
            uint32_t kh[4][4], klf[4][4];
#pragma unroll
            for (int p = 0; p < 4; p++) {
                const uint32_t koffb = (ks >> 1) * 4096u
                    + sw64((b_row + p * 16) * 64 + (ks & 1) * 32 + b_c16);
                ldsm4(kh[p], Kh + koffb);
                ldsm4(klf[p], Kl + koffb);
            }
#pragma unroll
            for (int j = 0; j < 8; j++)
                mma_bf(sn[j], qh, &kh[j >> 1][(j & 1) * 2]);
#pragma unroll
            for (int j = 0; j < 8; j++)
                mma_bf(sn[j], qh, &klf[j >> 1][(j & 1) * 2]);
#pragma unroll
            for (int j = 0; j < 8; j++)
                mma_bf(sn[j], ql, &kh[j >> 1][(j & 1) * 2]);
        }
    };

    auto do_softmax_pv = [&](int kt, float (*s)[4]) {
        const bool diag = (kt >= nkt - 2);
        if (diag) {
            const int k0 = kt * 64;
#pragma unroll
            for (int j = 0; j < 8; j++)
#pragma unroll
                for (int e = 0; e < 4; e++) {
                    const int cglob = k0 + j * 8 + (lane & 3) * 2 + (e & 1);
                    const int rglob = q0 + w * 16 + (lane >> 2) + (e >> 1) * 8;
                    if (cglob > rglob) s[j][e] = NEG_BIG;
                }
        }

        float mx0 = NEG_BIG, mx1 = NEG_BIG;
#pragma unroll
        for (int j = 0; j < 8; j++) {
            mx0 = fmaxf(mx0, fmaxf(s[j][0], s[j][1]));
            mx1 = fmaxf(mx1, fmaxf(s[j][2], s[j][3]));
        }
        mx0 = fmaxf(mx0, __shfl_xor_sync(0xffffffffu, mx0, 1));
        mx0 = fmaxf(mx0, __shfl_xor_sync(0xffffffffu, mx0, 2));
        mx1 = fmaxf(mx1, __shfl_xor_sync(0xffffffffu, mx1, 1));
        mx1 = fmaxf(mx1, __shfl_xor_sync(0xffffffffu, mx1, 2));

        const float mn0 = fmaxf(m_prev[0], mx0);
        const float mn1 = fmaxf(m_prev[1], mx1);
        const float corr0 = ex2(m_prev[0] - mn0);
        const float corr1 = ex2(m_prev[1] - mn1);
        m_prev[0] = mn0;
        m_prev[1] = mn1;

        float rs0 = 0.f, rs1 = 0.f;
#pragma unroll
        for (int j = 0; j < 8; j++) {
            s[j][0] = ex2(s[j][0] - mn0);
            s[j][1] = ex2(s[j][1] - mn0);
            s[j][2] = ex2(s[j][2] - mn1);
            s[j][3] = ex2(s[j][3] - mn1);
            rs0 += s[j][0] + s[j][1];
            rs1 += s[j][2] + s[j][3];
        }
        rs0 += __shfl_xor_sync(0xffffffffu, rs0, 1);
        rs0 += __shfl_xor_sync(0xffffffffu, rs0, 2);
        rs1 += __shfl_xor_sync(0xffffffffu, rs1, 1);
        rs1 += __shfl_xor_sync(0xffffffffu, rs1, 2);
        l[0] = l[0] * corr0 + rs0;
        l[1] = l[1] * corr1 + rs1;

#pragma unroll
        for (int nt = 0; nt < 16; nt++) {
            o[nt][0] *= corr0; o[nt][1] *= corr0;
            o[nt][2] *= corr1; o[nt][3] *= corr1;
        }

        const uint32_t Vst = smV + (uint32_t)(kt & 1) * 16384u;
#pragma unroll
        for (int ks = 0; ks < 4; ks++) {
            const int j0 = 2 * ks, j1 = 2 * ks + 1;
            uint32_t pf[4];
            pf[0] = packhf(s[j0][0], s[j0][1]);
            pf[1] = packhf(s[j0][2], s[j0][3]);
            pf[2] = packhf(s[j1][0], s[j1][1]);
            pf[3] = packhf(s[j1][2], s[j1][3]);
#pragma unroll
            for (int c = 0; c < 4; c++) {
                uint32_t vh0[4], vh1[4];
                const uint32_t vb0 = c * 4096u + sw64((ks * 16 + v_row) * 64 + v_c16);
                const uint32_t vb1 = c * 4096u + sw64((ks * 16 + v_row) * 64 + 32 + v_c16);
                ldsm4t(vh0, Vst + vb0);
                ldsm4t(vh1, Vst + vb1);
                mma_hf(o[c * 4 + 0], pf, vh0 + 0);
                mma_hf(o[c * 4 + 1], pf, vh0 + 2);
                mma_hf(o[c * 4 + 2], pf, vh1 + 0);
                mma_hf(o[c * 4 + 3], pf, vh1 + 2);
            }
        }
    };

    CP_WAIT1();
    __syncthreads();
    do_qk(0, sA);

    auto body = [&](int i, float (*scur)[4], float (*snxt)[4]) {
        CP_WAIT0();
        __syncthreads();
        if (i + 1 < nkt) load_V((i + 1) & 1, i + 1);
        if (i + 2 < nkt) load_K((i + 2) & 1, i + 2);
        CP_COMMIT();
        if (i + 1 < nkt) do_qk(i + 1, snxt);
        do_softmax_pv(i, scur);
    };

    for (int i = 0; i < nkt; i += 2) {
        body(i, sA, sB);
        if (i + 1 < nkt) body(i + 1, sB, sA);
    }

    const float inv0 = 1.f / l[0];
    const float inv1 = 1.f / l[1];
    const int row0 = q0 + w * 16 + (lane >> 2);
#pragma unroll
    for (int nt = 0; nt < 16; nt++) {
        const int d = nt * 8 + (lane & 3) * 2;
        const size_t o0 = ((size_t)(b * SEQ + row0) * NHEADS + h) * HD + d;
        const size_t o1 = ((size_t)(b * SEQ + row0 + 8) * NHEADS + h) * HD + d;
        *(uint32_t*)&Oa[o0] = packhf(o[nt][0] * inv0, o[nt][1] * inv0);
        *(uint32_t*)&Oa[o1] = packhf(o[nt][2] * inv1, o[nt][3] * inv1);
    }
}

// ---------------------------------------------------------------------------
extern "C" void kernel_launch(void* const* d_in, const int* in_sizes, int n_in,
                              void* d_out, int out_size)
{
    const float* X    = (const float*)d_in[0];
    const float* cosb = (const float*)d_in[1];
    const float* sinb = (const float*)d_in[2];
    const float* wq = (const float*)d_in[4];
    const float* wk = (const float*)d_in[5];
    const float* wv = (const float*)d_in[6];
    const float* wo = (const float*)d_in[7];
    float* out = (float*)d_out;

    void *pq, *pk, *pv;
    cudaGetSymbolAddress(&pq, g_q);
    cudaGetSymbolAddress(&pk, g_k);
    cudaGetSymbolAddress(&pv, g_v);
    float* Qb = (float*)pq;
    float* Kb = (float*)pk;
    float* Vb = (float*)pv;

    void *pxf, *pwh, *pwl, *poh, *pol, *paf, *pvf;
    cudaGetSymbolAddress(&pxf, g_xf16);
    cudaGetSymbolAddress(&pwh, g_wqkvT_hi); cudaGetSymbolAddress(&pwl, g_wqkvT_lo);
    cudaGetSymbolAddress(&poh, g_woT_hi);   cudaGetSymbolAddress(&pol, g_woT_lo);
    cudaGetSymbolAddress(&paf, g_af16);
    cudaGetSymbolAddress(&pvf, g_vf16);
    __half *Xf = (__half*)pxf;
    __half *WHi = (__half*)pwh, *WLo = (__half*)pwl;
    __half *WoHi = (__half*)poh, *WoLo = (__half*)pol;
    __half *Af = (__half*)paf;
    __half *Vf = (__half*)pvf;

    void *pfqh, *pfql, *pfkh, *pfkl;
    cudaGetSymbolAddress(&pfqh, g_qhi); cudaGetSymbolAddress(&pfql, g_qlo);
    cudaGetSymbolAddress(&pfkh, g_khi); cudaGetSymbolAddress(&pfkl, g_klo);
    __nv_bfloat16 *FQh = (__nv_bfloat16*)pfqh, *FQl = (__nv_bfloat16*)pfql;
    __nv_bfloat16 *FKh = (__nv_bfloat16*)pfkh, *FKl = (__nv_bfloat16*)pfkl;

    static bool attr_set = false;
    if (!attr_set) {
        cudaFuncSetAttribute(gemm_hf<0>, cudaFuncAttributeMaxDynamicSharedMemorySize, GT_SMEM);
        cudaFuncSetAttribute(gemm_hf<1>, cudaFuncAttributeMaxDynamicSharedMemorySize, GT_SMEM);
        cudaFuncSetAttribute(flash_mma, cudaFuncAttributeMaxDynamicSharedMemorySize, FLB_SMEM);
        attr_set = true;
    }

    const int M = BATCH * SEQ;   // 4096

    // 1: X -> fp16
    cvt16_kernel<<<(M * HID / 4 + 255) / 256, 256>>>(X, Xf, M * HID);
    // 2: weights -> merged fp16 hi/lo [N,K]
    splitW_kernel<<<dim3(128, 128, 4), dim3(32, 8)>>>(
        wq, wk, wv, wo, WHi, WLo, WoHi, WoLo);
    // 3: merged QKV projection (N=6144, fp16 2-pass, scatter epilogue)
    gemm_hf<1><<<dim3(48, 32), 256, GT_SMEM>>>(Xf, WHi, WLo, Qb, Kb, Vb, M, 6144, HID);
    // 4: all flash preps (ropeQ + ropeK + cvtV)
    {
        int total = PREP_QT + PREP_KT + PREP_VT;
        prep_kernel<<<(total + 255) / 256, 256>>>(Qb, Kb, Vb, cosb, sinb,
                                                  FQh, FQl, FKh, FKl, Vf);
    }
    // 5+6: flash attention (two half-grid launches -> ncu capture slot)
    flash_mma<<<dim3(NQT, 32), 256, FLB_SMEM>>>(FQh, FQl, FKh, FKl, Vf, Af, 0);
    flash_mma<<<dim3(NQT, 32), 256, FLB_SMEM>>>(FQh, FQl, FKh, FKl, Vf, Af, 32);
    // 7: output projection
    gemm_hf<0><<<dim3(32, 32), 256, GT_SMEM>>>(Af, WoHi, WoLo, out, out, out, M, HID, 4096);

    (void)in_sizes; (void)n_in; (void)out_size;
}

// round 11
// speedup vs baseline: 1.9504x; 1.1489x over previous
#include <cuda_runtime.h>
#include <cuda_bf16.h>
#include <cuda_fp16.h>
#include <math.h>
#include <stdint.h>

// Problem constants
#define BATCH   2
#define SEQ     2048
#define HID     4096
#define NHEADS  32
#define NKV     8
#define NREP    4
#define HD      128
#define SCALING 0.08838834764831845f           // 128^-0.5
#define QSCALE  0.1275429555686623f            // SCALING * log2(e)
#define NEG_BIG (-1.0e30f)

// ---------------------------------------------------------------------------
// Scratch (device globals)
// ---------------------------------------------------------------------------
__device__ float g_q[BATCH * NHEADS * SEQ * HD];
__device__ float g_k[BATCH * NKV * SEQ * HD];
__device__ float g_v[BATCH * NKV * SEQ * HD];

// fp16 GEMM operands
__device__ __half g_xf16[4096 * 4096];
__device__ __half g_wqkvT_hi[6144 * 4096], g_wqkvT_lo[6144 * 4096];  // merged QKV [N,K]
__device__ __half g_woT_hi[4096 * 4096];                             // wo single fp16
__device__ __half g_af16[4096 * 4096];                               // attn out fp16

// flash operands: Q/K bf16 hi/lo (3-pass QK), V fp16 single
__device__ __nv_bfloat16 g_qhi[BATCH * NHEADS * SEQ * HD], g_qlo[BATCH * NHEADS * SEQ * HD];
__device__ __nv_bfloat16 g_khi[BATCH * NKV * SEQ * HD],    g_klo[BATCH * NKV * SEQ * HD];
__device__ __half        g_vf16[BATCH * NKV * SEQ * HD];

// ---------------------------------------------------------------------------
// PTX helpers
// ---------------------------------------------------------------------------
__device__ __forceinline__ uint32_t smem_u32(const void* p) {
    uint32_t a;
    asm("{ .reg .u64 t; cvta.to.shared.u64 t, %1; cvt.u32.u64 %0, t; }"
        : "=r"(a) : "l"(p));
    return a;
}

#define CP_ASYNC16(dst, src) \
    asm volatile("cp.async.cg.shared.global [%0], [%1], 16;" :: "r"(dst), "l"(src) : "memory")
#define CP_COMMIT() asm volatile("cp.async.commit_group;" ::: "memory")
#define CP_WAIT0()  asm volatile("cp.async.wait_group 0;" ::: "memory")
#define CP_WAIT1()  asm volatile("cp.async.wait_group 1;" ::: "memory")

__device__ __forceinline__ void ldsm4(uint32_t* r, uint32_t addr) {
    asm volatile("ldmatrix.sync.aligned.m8n8.x4.shared.b16 {%0,%1,%2,%3}, [%4];"
        : "=r"(r[0]), "=r"(r[1]), "=r"(r[2]), "=r"(r[3]) : "r"(addr));
}
__device__ __forceinline__ void ldsm4t(uint32_t* r, uint32_t addr) {
    asm volatile("ldmatrix.sync.aligned.m8n8.x4.trans.shared.b16 {%0,%1,%2,%3}, [%4];"
        : "=r"(r[0]), "=r"(r[1]), "=r"(r[2]), "=r"(r[3]) : "r"(addr));
}

__device__ __forceinline__ void mma_bf(float* d, const uint32_t* a, const uint32_t* b) {
    asm volatile(
        "mma.sync.aligned.m16n8k16.row.col.f32.bf16.bf16.f32 "
        "{%0,%1,%2,%3}, {%4,%5,%6,%7}, {%8,%9}, {%0,%1,%2,%3};"
        : "+f"(d[0]), "+f"(d[1]), "+f"(d[2]), "+f"(d[3])
        : "r"(a[0]), "r"(a[1]), "r"(a[2]), "r"(a[3]), "r"(b[0]), "r"(b[1]));
}
__device__ __forceinline__ void mma_hf(float* d, const uint32_t* a, const uint32_t* b) {
    asm volatile(
        "mma.sync.aligned.m16n8k16.row.col.f32.f16.f16.f32 "
        "{%0,%1,%2,%3}, {%4,%5,%6,%7}, {%8,%9}, {%0,%1,%2,%3};"
        : "+f"(d[0]), "+f"(d[1]), "+f"(d[2]), "+f"(d[3])
        : "r"(a[0]), "r"(a[1]), "r"(a[2]), "r"(a[3]), "r"(b[0]), "r"(b[1]));
}

__device__ __forceinline__ uint32_t sw64(uint32_t off) {
    return off ^ ((off >> 3) & 0x30);
}
__device__ __forceinline__ uint32_t sw128(uint32_t off) {
    return off ^ ((off >> 3) & 0x70);
}

__device__ __forceinline__ uint32_t packhf(float lo, float hi) {
    uint32_t r;
    asm("cvt.rn.f16x2.f32 %0, %1, %2;" : "=r"(r) : "f"(hi), "f"(lo));
    return r;
}

__device__ __forceinline__ float ex2(float x) {
    float r;
    asm("ex2.approx.f32 %0, %1;" : "=f"(r) : "f"(x));
    return r;
}

// ---------------------------------------------------------------------------
// prepW: z=0..2 -> merged QKV weight transpose+split; z=3 -> wo (hi only);
//        z=4 -> X fp32->fp16 convert.
// ---------------------------------------------------------------------------
__global__ void prepW_kernel(
    const float* __restrict__ X,
    const float* __restrict__ wq, const float* __restrict__ wk,
    const float* __restrict__ wv, const float* __restrict__ wo,
    __half* __restrict__ Xf,
    __half* __restrict__ qkvh, __half* __restrict__ qkvl,
    __half* __restrict__ oh)
{
    const int z = blockIdx.z;
    const int tx = threadIdx.x, ty = threadIdx.y;

    if (z == 4) {
        // linear X convert: 4 floats/thread
        size_t g = ((size_t)blockIdx.y * gridDim.x + blockIdx.x) * 256 + (ty * 32 + tx);
        size_t i = g * 4;
        float4 v = *(const float4*)(X + i);
        uint32_t p0 = packhf(v.x, v.y);
        uint32_t p1 = packhf(v.z, v.w);
        *(uint2*)(Xf + i) = make_uint2(p0, p1);
        return;
    }

    const float* in;
    int N, rbase;
    bool want_lo;
    __half *hi, *lo;
    if (z == 0)      { in = wq; hi = qkvh; lo = qkvl; N = 4096; rbase = 0;    want_lo = true; }
    else if (z == 1) { in = wk; hi = qkvh; lo = qkvl; N = 1024; rbase = 4096; want_lo = true; }
    else if (z == 2) { in = wv; hi = qkvh; lo = qkvl; N = 1024; rbase = 5120; want_lo = true; }
    else             { in = wo; hi = oh;   lo = oh;   N = 4096; rbase = 0;    want_lo = false; }
    const int n0 = blockIdx.x * 32;
    if (n0 >= N) return;
    const int K = 4096;
    const int k0 = blockIdx.y * 32;

    __shared__ float t[32][33];
    for (int i = ty; i < 32; i += 8)
        t[i][tx] = in[(size_t)(k0 + i) * N + n0 + tx];
    __syncthreads();
    for (int i = ty; i < 32; i += 8) {
        float a = t[tx][i];
        __half h = __float2half_rn(a);
        size_t o = (size_t)(rbase + n0 + i) * K + k0 + tx;
        hi[o] = h;
        if (want_lo)
            lo[o] = __float2half_rn(a - __half2float(h));
    }
}

// ---------------------------------------------------------------------------
// prep: ropeQ + ropeK (bf16 hi/lo) + cvtV (fp16), one launch
// ---------------------------------------------------------------------------
#define PREP_QT (BATCH * NHEADS * SEQ * 64)
#define PREP_KT (BATCH * NKV * SEQ * 64)
#define PREP_VT (BATCH * NKV * SEQ * HD / 4)

__device__ __forceinline__ void rope_one(
    const float* __restrict__ x, const float* __restrict__ cosb,
    const float* __restrict__ sinb, __nv_bfloat16* __restrict__ hi,
    __nv_bfloat16* __restrict__ lo, int nh, float scale, int idx)
{
    const int d = idx & 63;
    const int row = idx >> 6;
    const int s = row & (SEQ - 1);
    const int b = (row / SEQ) / nh;
    const float* xr = x + (size_t)row * HD;
    const float* cb = cosb + ((size_t)b * SEQ + s) * HD;
    const float* sb = sinb + ((size_t)b * SEQ + s) * HD;
    const float x0 = xr[d];
    const float x1 = xr[d + 64];
    const float y0 = (x0 * cb[d]      - x1 * sb[d])      * scale;
    const float y1 = (x1 * cb[d + 64] + x0 * sb[d + 64]) * scale;
    const size_t o = (size_t)row * HD + d;
    __nv_bfloat16 h0 = __float2bfloat16(y0);
    __nv_bfloat16 h1 = __float2bfloat16(y1);
    hi[o]      = h0;
    hi[o + 64] = h1;
    lo[o]      = __float2bfloat16(y0 - __bfloat162float(h0));
    lo[o + 64] = __float2bfloat16(y1 - __bfloat162float(h1));
}

__global__ void prep_kernel(
    const float* __restrict__ Qb, const float* __restrict__ Kb,
    const float* __restrict__ Vb,
    const float* __restrict__ cosb, const float* __restrict__ sinb,
    __nv_bfloat16* __restrict__ FQh, __nv_bfloat16* __restrict__ FQl,
    __nv_bfloat16* __restrict__ FKh, __nv_bfloat16* __restrict__ FKl,
    __half* __restrict__ Vf)
{
    int idx = blockIdx.x * blockDim.x + threadIdx.x;
    if (idx < PREP_QT) {
        rope_one(Qb, cosb, sinb, FQh, FQl, NHEADS, QSCALE, idx);
    } else if (idx < PREP_QT + PREP_KT) {
        rope_one(Kb, cosb, sinb, FKh, FKl, NKV, 1.0f, idx - PREP_QT);
    } else if (idx < PREP_QT + PREP_KT + PREP_VT) {
        int i = (idx - PREP_QT - PREP_KT) * 4;
        float4 v = *(const float4*)(Vb + i);
        uint32_t p0 = packhf(v.x, v.y);
        uint32_t p1 = packhf(v.z, v.w);
        *(uint2*)(Vf + i) = make_uint2(p0, p1);
    }
}

// ---------------------------------------------------------------------------
// fp16 GEMM, BK=64, BM=BN=128, 256 threads, 2-stage cp.async.
// NPASS=2: C = A @ (Bhi+Blo)^T (stage 48KB). NPASS=1: C = A @ Bhi^T (stage 32KB).
// MODE 0: row-major out. MODE 1: merged-QKV scatter.
// ---------------------------------------------------------------------------
template <int MODE, int NPASS>
__global__ __launch_bounds__(256, 2) void gemm_hf(
    const __half* __restrict__ A,
    const __half* __restrict__ Bhi, const __half* __restrict__ Blo,
    float* __restrict__ Qo, float* __restrict__ Ko, float* __restrict__ Vo,
    int M, int N, int K)
{
    constexpr uint32_t STAGE = (NPASS == 2) ? 49152u : 32768u;
    extern __shared__ char dsm[];
    const uint32_t sm_base = smem_u32(dsm);

    const int tid = threadIdx.x;
    const int wid = tid >> 5;
    const int lane = tid & 31;
    const int wm = wid & 3;
    const int wn = wid >> 2;
    const int m0 = blockIdx.y * 128;
    const int n0 = blockIdx.x * 128;

    auto load_chunk = [&](int stage, int c) {
        const int k0 = c << 6;
        const uint32_t stb = sm_base + stage * STAGE;
        if (NPASS == 2) {
#pragma unroll
            for (int it = 0; it < 12; it++) {
                int g = tid + it * 256;
                int arr = g >> 10;
                int rem = g & 1023;
                int r = rem >> 3;
                int gg = rem & 7;
                int rowg = (arr == 0 ? m0 : n0) + r;
                const __half* base = (arr == 0) ? A : (arr == 1 ? Bhi : Blo);
                const __half* src = base + (size_t)rowg * K + k0 + gg * 8;
                uint32_t off = sw128((uint32_t)(r * 128 + gg * 16));
                CP_ASYNC16(stb + arr * 16384u + off, src);
            }
        } else {
#pragma unroll
            for (int it = 0; it < 8; it++) {
                int g = tid + it * 256;
                int arr = g >> 10;
                int rem = g & 1023;
                int r = rem >> 3;
                int gg = rem & 7;
                int rowg = (arr == 0 ? m0 : n0) + r;
                const __half* base = (arr == 0) ? A : Bhi;
                const __half* src = base + (size_t)rowg * K + k0 + gg * 8;
                uint32_t off = sw128((uint32_t)(r * 128 + gg * 16));
                CP_ASYNC16(stb + arr * 16384u + off, src);
            }
        }
        CP_COMMIT();
    };

    float acc[2][8][4];
#pragma unroll
    for (int mt = 0; mt < 2; mt++)
#pragma unroll
        for (int nt = 0; nt < 8; nt++)
#pragma unroll
            for (int i = 0; i < 4; i++) acc[mt][nt][i] = 0.f;

    const int NC = K >> 6;
    load_chunk(0, 0);

    const uint32_t a_row = wm * 32 + (lane & 15);
    const uint32_t a_c16 = (lane >> 4) * 16;
    const uint32_t b_row = wn * 64 + ((lane >> 4) & 1) * 8 + (lane & 7);
    const uint32_t b_c16 = ((lane >> 3) & 1) * 16;

    for (int c = 0; c < NC; c++) {
        if (c + 1 < NC) {
            load_chunk((c + 1) & 1, c + 1);
            CP_WAIT1();
        } else {
            CP_WAIT0();
        }
        __syncthreads();

        const uint32_t stb = sm_base + (uint32_t)(c & 1) * STAGE;
        const uint32_t Ab = stb, Bh = stb + 16384u, Bl = stb + 32768u;

#pragma unroll
        for (int kt = 0; kt < 4; kt++) {
            uint32_t af[2][4], bhf[4][4], blf[4][4];
#pragma unroll
            for (int mt = 0; mt < 2; mt++) {
                uint32_t off = sw128((a_row + mt * 16) * 128 + kt * 32 + a_c16);
                ldsm4(af[mt], Ab + off);
            }
#pragma unroll
            for (int p = 0; p < 4; p++) {
                uint32_t off = sw128((b_row + p * 16) * 128 + kt * 32 + b_c16);
                ldsm4(bhf[p], Bh + off);
                if (NPASS == 2) ldsm4(blf[p], Bl + off);
            }
#pragma unroll
            for (int mt = 0; mt < 2; mt++)
#pragma unroll
                for (int nt = 0; nt < 8; nt++)
                    mma_hf(acc[mt][nt], af[mt], &bhf[nt >> 1][(nt & 1) * 2]);
            if (NPASS == 2) {
#pragma unroll
                for (int mt = 0; mt < 2; mt++)
#pragma unroll
                    for (int nt = 0; nt < 8; nt++)
                        mma_hf(acc[mt][nt], af[mt], &blf[nt >> 1][(nt & 1) * 2]);
            }
        }
        __syncthreads();
    }

    const int mr = m0 + wm * 32 + (lane >> 2);
    const int nc = n0 + wn * 64 + (lane & 3) * 2;
#pragma unroll
    for (int mt = 0; mt < 2; mt++) {
#pragma unroll
        for (int nt = 0; nt < 8; nt++) {
#pragma unroll
            for (int half = 0; half < 2; half++) {
                const int m = mr + mt * 16 + half * 8;
                const int n = nc + nt * 8;
                float2 v = make_float2(acc[mt][nt][half * 2], acc[mt][nt][half * 2 + 1]);
                if (MODE == 0) {
                    *(float2*)&Qo[(size_t)m * N + n] = v;
                } else {
                    const int b = m >> 11;
                    const int s = m & (SEQ - 1);
                    const int d = n & (HD - 1);
                    if (n < 4096) {
                        const int h = n >> 7;
                        *(float2*)&Qo[((size_t)(b * NHEADS + h) * SEQ + s) * HD + d] = v;
                    } else if (n < 5120) {
                        const int kv = (n - 4096) >> 7;
                        *(float2*)&Ko[((size_t)(b * NKV + kv) * SEQ + s) * HD + d] = v;
                    } else {
                        const int kv = (n - 5120) >> 7;
                        *(float2*)&Vo[((size_t)(b * NKV + kv) * SEQ + s) * HD + d] = v;
                    }
                }
            }
        }
    }
}

#define GT_SMEM_P2 (2 * 49152)
#define GT_SMEM_P1 (2 * 32768)

// ---------------------------------------------------------------------------
// Flash attention v4 (unchanged math): Br=128, Bc=64, 256 threads.
// QK bf16 3-pass pipelined; PV fp16 single. Two launches via bh_base.
// ---------------------------------------------------------------------------
#define FLB_SMEM (65536 + 65536 + 32768)
#define NQT (SEQ / 128)   // 16

__global__ __launch_bounds__(256) void flash_mma(
    const __nv_bfloat16* __restrict__ Qhi, const __nv_bfloat16* __restrict__ Qlo,
    const __nv_bfloat16* __restrict__ Khi, const __nv_bfloat16* __restrict__ Klo,
    const __half* __restrict__ Vf,
    __half* __restrict__ Oa, int bh_base)
{
    extern __shared__ char dsm[];
    const uint32_t smQ = smem_u32(dsm);
    const uint32_t smK = smQ + 65536u;
    const uint32_t smV = smK + 65536u;

    const int tid = threadIdx.x;
    const int w = tid >> 5;
    const int lane = tid & 31;
    const int qt = NQT - 1 - blockIdx.x;
    const int bh = bh_base + blockIdx.y;
    const int b = bh / NHEADS;
    const int h = bh % NHEADS;
    const int kvh = h / NREP;
    const int q0 = qt * 128;

    const size_t qoff = ((size_t)(b * NHEADS + h) * SEQ + q0) * HD;
    const size_t kvbase = (size_t)(b * NKV + kvh) * SEQ * HD;

    auto load_K = [&](int stage, int kt) {
        const int k0 = kt * 64;
        const uint32_t stb = smK + stage * 32768u;
#pragma unroll
        for (int it = 0; it < 8; it++) {
            int g = tid + it * 256;
            int arr = g >> 10;
            int rem = g & 1023;
            int r = rem >> 4;
            int gg = rem & 15;
            const __nv_bfloat16* src = (arr ? Klo : Khi) + kvbase + (size_t)(k0 + r) * HD + gg * 8;
            uint32_t dst = stb + arr * 16384u + (gg >> 2) * 4096u
                         + sw64((uint32_t)(r * 64 + (gg & 3) * 16));
            CP_ASYNC16(dst, src);
        }
    };
    auto load_V = [&](int stage, int kt) {
        const int k0 = kt * 64;
        const uint32_t stb = smV + stage * 16384u;
#pragma unroll
        for (int it = 0; it < 4; it++) {
            int g = tid + it * 256;
            int r = g >> 4;
            int gg = g & 15;
            const __half* src = Vf + kvbase + (size_t)(k0 + r) * HD + gg * 8;
            uint32_t dst = stb + (gg >> 2) * 4096u
                         + sw64((uint32_t)(r * 64 + (gg & 3) * 16));
            CP_ASYNC16(dst, src);
        }
    };

    {
#pragma unroll
        for (int it = 0; it < 16; it++) {
            int g = tid + it * 256;
            int arr = g >> 11;
            int rem = g & 2047;
            int r = rem >> 4;
            int gg = rem & 15;
            const __nv_bfloat16* src = (arr ? Qlo : Qhi) + qoff + (size_t)r * HD + gg * 8;
            uint32_t dst = smQ + arr * 32768u + (gg >> 2) * 8192u
                         + sw64((uint32_t)(r * 64 + (gg & 3) * 16));
            CP_ASYNC16(dst, src);
        }
    }
    load_K(0, 0);
    CP_COMMIT();
    const int nkt = 2 * qt + 2;
    if (nkt > 1) load_K(1, 1);
    load_V(0, 0);
    CP_COMMIT();

    float o[16][4];
#pragma unroll
    for (int nt = 0; nt < 16; nt++)
#pragma unroll
        for (int e = 0; e < 4; e++) o[nt][e] = 0.f;
    float m_prev[2] = {NEG_BIG, NEG_BIG};
    float l[2] = {0.f, 0.f};

    const uint32_t a_row = w * 16 + (lane & 15);
    const uint32_t a_c16 = (lane >> 4) * 16;
    const uint32_t b_row = ((lane >> 4) & 1) * 8 + (lane & 7);
    const uint32_t b_c16 = ((lane >> 3) & 1) * 16;
    const uint32_t v_row = (lane & 7) + ((lane >> 3) & 1) * 8;
    const uint32_t v_c16 = (lane >> 4) * 16;

    float sA[8][4], sB[8][4];

    auto do_qk = [&](int kt, float (*sn)[4]) {
        const uint32_t Kst = smK + (uint32_t)(kt & 1) * 32768u;
        const uint32_t Kh = Kst, Kl = Kst + 16384u;
#pragma unroll
        for (int j = 0; j < 8; j++)
#pragma unroll
            for (int e = 0; e < 4; e++) sn[j][e] = 0.f;
#pragma unroll
        for (int ks = 0; ks < 8; ks++) {
            const uint32_t qoffb = (ks >> 1) * 8192u
                + sw64(a_row * 64 + (ks & 1) * 32 + a_c16);
            uint32_t qh[4], ql[4];
            ldsm4(qh, smQ + qoffb);
            ldsm4(ql, smQ + 32768u + qoffb);
            uint32_t kh[4][4], klf[4][4];
#pragma unroll
            for (int p = 0; p < 4; p++) {
                const uint32_t koffb = (ks >> 1) * 4096u
                    + sw64((b_row + p * 16) * 64 + (ks & 1) * 32 + b_c16);
                ldsm4(kh[p], Kh + koffb);
                ldsm4(klf[p], Kl + koffb);
            }
#pragma unroll
            for (int j = 0; j < 8; j++)
                mma_bf(sn[j], qh, &kh[j >> 1][(j & 1) * 2]);
#pragma unroll
            for (int j = 0; j < 8; j++)
                mma_bf(sn[j], qh, &klf[j >> 1][(j & 1) * 2]);
#pragma unroll
            for (int j = 0; j < 8; j++)
                mma_bf(sn[j], ql, &kh[j >> 1][(j & 1) * 2]);
        }
    };

    auto do_softmax_pv = [&](int kt, float (*s)[4]) {
        const bool diag = (kt >= nkt - 2);
        if (diag) {
            const int k0 = kt * 64;
#pragma unroll
            for (int j = 0; j < 8; j++)
#pragma unroll
                for (int e = 0; e < 4; e++) {
                    const int cglob = k0 + j * 8 + (lane & 3) * 2 + (e & 1);
                    const int rglob = q0 + w * 16 + (lane >> 2) + (e >> 1) * 8;
                    if (cglob > rglob) s[j][e] = NEG_BIG;
                }
        }

        float mx0 = NEG_BIG, mx1 = NEG_BIG;
#pragma unroll
        for (int j = 0; j < 8; j++) {
            mx0 = fmaxf(mx0, fmaxf(s[j][0], s[j][1]));
            mx1 = fmaxf(mx1, fmaxf(s[j][2], s[j][3]));
        }
        mx0 = fmaxf(mx0, __shfl_xor_sync(0xffffffffu, mx0, 1));
        mx0 = fmaxf(mx0, __shfl_xor_sync(0xffffffffu, mx0, 2));
        mx1 = fmaxf(mx1, __shfl_xor_sync(0xffffffffu, mx1, 1));
        mx1 = fmaxf(mx1, __shfl_xor_sync(0xffffffffu, mx1, 2));

        const float mn0 = fmaxf(m_prev[0], mx0);
        const float mn1 = fmaxf(m_prev[1], mx1);
        const float corr0 = ex2(m_prev[0] - mn0);
        const float corr1 = ex2(m_prev[1] - mn1);
        m_prev[0] = mn0;
        m_prev[1] = mn1;

        float rs0 = 0.f, rs1 = 0.f;
#pragma unroll
        for (int j = 0; j < 8; j++) {
            s[j][0] = ex2(s[j][0] - mn0);
            s[j][1] = ex2(s[j][1] - mn0);
            s[j][2] = ex2(s[j][2] - mn1);
            s[j][3] = ex2(s[j][3] - mn1);
            rs0 += s[j][0] + s[j][1];
            rs1 += s[j][2] + s[j][3];
        }
        rs0 += __shfl_xor_sync(0xffffffffu, rs0, 1);
        rs0 += __shfl_xor_sync(0xffffffffu, rs0, 2);
        rs1 += __shfl_xor_sync(0xffffffffu, rs1, 1);
        rs1 += __shfl_xor_sync(0xffffffffu, rs1, 2);
        l[0] = l[0] * corr0 + rs0;
        l[1] = l[1] * corr1 + rs1;

#pragma unroll
        for (int nt = 0; nt < 16; nt++) {
            o[nt][0] *= corr0; o[nt][1] *= corr0;
            o[nt][2] *= corr1; o[nt][3] *= corr1;
        }

        const uint32_t Vst = smV + (uint32_t)(kt & 1) * 16384u;
#pragma unroll
        for (int ks = 0; ks < 4; ks++) {
            const int j0 = 2 * ks, j1 = 2 * ks + 1;
            uint32_t pf[4];
            pf[0] = packhf(s[j0][0], s[j0][1]);
            pf[1] = packhf(s[j0][2], s[j0][3]);
            pf[2] = packhf(s[j1][0], s[j1][1]);
            pf[3] = packhf(s[j1][2], s[j1][3]);
#pragma unroll
            for (int c = 0; c < 4; c++) {
                uint32_t vh0[4], vh1[4];
                const uint32_t vb0 = c * 4096u + sw64((ks * 16 + v_row) * 64 + v_c16);
                const uint32_t vb1 = c * 4096u + sw64((ks * 16 + v_row) * 64 + 32 + v_c16);
                ldsm4t(vh0, Vst + vb0);
                ldsm4t(vh1, Vst + vb1);
                mma_hf(o[c * 4 + 0], pf, vh0 + 0);
                mma_hf(o[c * 4 + 1], pf, vh0 + 2);
                mma_hf(o[c * 4 + 2], pf, vh1 + 0);
                mma_hf(o[c * 4 + 3], pf, vh1 + 2);
            }
        }
    };

    CP_WAIT1();
    __syncthreads();
    do_qk(0, sA);

    auto body = [&](int i, float (*scur)[4], float (*snxt)[4]) {
        CP_WAIT0();
        __syncthreads();
        if (i + 1 < nkt) load_V((i + 1) & 1, i + 1);
        if (i + 2 < nkt) load_K((i + 2) & 1, i + 2);
        CP_COMMIT();
        if (i + 1 < nkt) do_qk(i + 1, snxt);
        do_softmax_pv(i, scur);
    };

    for (int i = 0; i < nkt; i += 2) {
        body(i, sA, sB);
        if (i + 1 < nkt) body(i + 1, sB, sA);
    }

    const float inv0 = 1.f / l[0];
    const float inv1 = 1.f / l[1];
    const int row0 = q0 + w * 16 + (lane >> 2);
#pragma unroll
    for (int nt = 0; nt < 16; nt++) {
        const int d = nt * 8 + (lane & 3) * 2;
        const size_t o0 = ((size_t)(b * SEQ + row0) * NHEADS + h) * HD + d;
        const size_t o1 = ((size_t)(b * SEQ + row0 + 8) * NHEADS + h) * HD + d;
        *(uint32_t*)&Oa[o0] = packhf(o[nt][0] * inv0, o[nt][1] * inv0);
        *(uint32_t*)&Oa[o1] = packhf(o[nt][2] * inv1, o[nt][3] * inv1);
    }
}

// ---------------------------------------------------------------------------
extern "C" void kernel_launch(void* const* d_in, const int* in_sizes, int n_in,
                              void* d_out, int out_size)
{
    const float* X    = (const float*)d_in[0];
    const float* cosb = (const float*)d_in[1];
    const float* sinb = (const float*)d_in[2];
    const float* wq = (const float*)d_in[4];
    const float* wk = (const float*)d_in[5];
    const float* wv = (const float*)d_in[6];
    const float* wo = (const float*)d_in[7];
    float* out = (float*)d_out;

    void *pq, *pk, *pv;
    cudaGetSymbolAddress(&pq, g_q);
    cudaGetSymbolAddress(&pk, g_k);
    cudaGetSymbolAddress(&pv, g_v);
    float* Qb = (float*)pq;
    float* Kb = (float*)pk;
    float* Vb = (float*)pv;

    void *pxf, *pwh, *pwl, *poh, *paf, *pvf;
    cudaGetSymbolAddress(&pxf, g_xf16);
    cudaGetSymbolAddress(&pwh, g_wqkvT_hi); cudaGetSymbolAddress(&pwl, g_wqkvT_lo);
    cudaGetSymbolAddress(&poh, g_woT_hi);
    cudaGetSymbolAddress(&paf, g_af16);
    cudaGetSymbolAddress(&pvf, g_vf16);
    __half *Xf = (__half*)pxf;
    __half *WHi = (__half*)pwh, *WLo = (__half*)pwl;
    __half *WoHi = (__half*)poh;
    __half *Af = (__half*)paf;
    __half *Vf = (__half*)pvf;

    void *pfqh, *pfql, *pfkh, *pfkl;
    cudaGetSymbolAddress(&pfqh, g_qhi); cudaGetSymbolAddress(&pfql, g_qlo);
    cudaGetSymbolAddress(&pfkh, g_khi); cudaGetSymbolAddress(&pfkl, g_klo);
    __nv_bfloat16 *FQh = (__nv_bfloat16*)pfqh, *FQl = (__nv_bfloat16*)pfql;
    __nv_bfloat16 *FKh = (__nv_bfloat16*)pfkh, *FKl = (__nv_bfloat16*)pfkl;

    static bool attr_set = false;
    if (!attr_set) {
        cudaFuncSetAttribute((const void*)gemm_hf<1, 2>,
                             cudaFuncAttributeMaxDynamicSharedMemorySize, GT_SMEM_P2);
        cudaFuncSetAttribute((const void*)gemm_hf<0, 1>,
                             cudaFuncAttributeMaxDynamicSharedMemorySize, GT_SMEM_P1);
        cudaFuncSetAttribute((const void*)flash_mma,
                             cudaFuncAttributeMaxDynamicSharedMemorySize, FLB_SMEM);
        attr_set = true;
    }

    const int M = BATCH * SEQ;   // 4096

    // 1: all weight prep + X convert in one launch
    prepW_kernel<<<dim3(128, 128, 5), dim3(32, 8)>>>(
        X, wq, wk, wv, wo, Xf, WHi, WLo, WoHi);
    // 2: merged QKV projection (2-pass)
    gemm_hf<1, 2><<<dim3(48, 32), 256, GT_SMEM_P2>>>(Xf, WHi, WLo, Qb, Kb, Vb, M, 6144, HID);
    // 3: flash preps (ropeQ + ropeK + cvtV)
    {
        int total = PREP_QT + PREP_KT + PREP_VT;
        prep_kernel<<<(total + 255) / 256, 256>>>(Qb, Kb, Vb, cosb, sinb,
                                                  FQh, FQl, FKh, FKl, Vf);
    }
    // 4+5: flash attention (slot 4 = ncu capture)
    flash_mma<<<dim3(NQT, 32), 256, FLB_SMEM>>>(FQh, FQl, FKh, FKl, Vf, Af, 0);
    flash_mma<<<dim3(NQT, 32), 256, FLB_SMEM>>>(FQh, FQl, FKh, FKl, Vf, Af, 32);
    // 6: output projection (single-pass fp16)
    gemm_hf<0, 1><<<dim3(32, 32), 256, GT_SMEM_P1>>>(Af, WoHi, WoHi, out, out, out, M, HID, 4096);

    (void)in_sizes; (void)n_in; (void)out_size;
}